// round 3
// baseline (speedup 1.0000x reference)
#include <cuda_runtime.h>
#include <cuda_bf16.h>

// Problem constants
#define BB   16
#define NN   1024
#define DD   128
#define EE   16384
#define AA   64
#define DIAM 3
#define CH   64           // edge chunks for CSR build
#define CE   (EE / CH)    // 256 edges per chunk

// ---------------- device scratch (no allocations allowed) ----------------
__device__ float g_h[BB * NN * DD];          // node state            8 MB
__device__ float g_big[BB * NN * 640];       // [hs|ht|gh] per node  41.9 MB
__device__ float g_agg[BB * NN * DD];        // aggregated messages   8 MB
__device__ float g_ef[BB * EE];              // edge scalars, CSR slot order
__device__ float g_Wbig[128 * 640];          // packed [Ws|Wt|Whh^T]
__device__ float g_bias1[640];               // [0,0,b_hh]
__device__ float g_Wiht[128 * 384];          // W_ih transposed
__device__ int   g_ccnt[CH * NN];            // per-chunk per-node counts -> offsets
__device__ int   g_deg[NN];
__device__ int   g_off[NN + 1];
__device__ int   g_eid[EE];                  // CSR: edge ids sorted by tgt (stable)
__device__ int   g_esrc[EE];                 // CSR: src node per slot
__device__ float g_part[BB * 16 * DD];       // pooling partials

__device__ __forceinline__ float selu_f(float x) {
    const float sc = 1.0507009873554805f, al = 1.6732632423543772f;
    return x > 0.f ? sc * x : sc * al * (__expf(x) - 1.f);
}

// ---------------- setup kernels ----------------
__global__ void k_pack(const float* __restrict__ Wmsg, const float* __restrict__ Whh,
                       const float* __restrict__ bhh, const float* __restrict__ Wih) {
    int t = blockIdx.x * blockDim.x + threadIdx.x;
    if (t < 128 * 640) {
        int k = t / 640, c = t % 640;
        float v;
        if (c < 128)       v = Wmsg[k * 128 + c];                 // src part
        else if (c < 256)  v = Wmsg[(128 + k) * 128 + (c - 128)]; // tgt part
        else               v = Whh[(c - 256) * 128 + k];          // W_hh^T
        g_Wbig[k * 640 + c] = v;
    }
    if (t < 640) g_bias1[t] = (t < 256) ? 0.f : bhh[t - 256];
    if (t < 128 * 384) {
        int k = t / 384, j = t % 384;
        g_Wiht[k * 384 + j] = Wih[j * 128 + k];
    }
}

// ---- CSR build: chunked histogram (deterministic stable order) ----
__global__ void k_cnt(const int* __restrict__ tgt) {  // grid CH, block 256
    __shared__ int c[NN];
    for (int i = threadIdx.x; i < NN; i += 256) c[i] = 0;
    __syncthreads();
    int e = blockIdx.x * CE + threadIdx.x;
    atomicAdd(&c[tgt[e]], 1);
    __syncthreads();
    for (int i = threadIdx.x; i < NN; i += 256) g_ccnt[blockIdx.x * NN + i] = c[i];
}

__global__ void k_tot() {  // grid 8, block 128: per-node totals (coalesced)
    int n = blockIdx.x * 128 + threadIdx.x;
    int s = 0;
#pragma unroll
    for (int c = 0; c < CH; ++c) s += g_ccnt[c * NN + n];
    g_deg[n] = s;
}

__global__ void k_scanx() {  // 1 block, 1024 threads: node prefix scan
    __shared__ int s[NN];
    int n = threadIdx.x;
    s[n] = g_deg[n];
    __syncthreads();
    for (int o = 1; o < NN; o <<= 1) {
        int x = (n >= o) ? s[n - o] : 0;
        __syncthreads();
        s[n] += x;
        __syncthreads();
    }
    g_off[n + 1] = s[n];
    if (n == 0) g_off[0] = 0;
}

__global__ void k_offk() {  // grid 8, block 128: chunk offsets per node
    int n = blockIdx.x * 128 + threadIdx.x;
    int run = g_off[n];
#pragma unroll
    for (int c = 0; c < CH; ++c) {
        int v = g_ccnt[c * NN + n];
        g_ccnt[c * NN + n] = run;
        run += v;
    }
}

// stable fill: one warp per chunk, edges processed in ascending e order
__global__ void k_fill(const int* __restrict__ tgt, const int* __restrict__ src) {
    __shared__ int ctr[NN];
    int lane = threadIdx.x;
    int chunk = blockIdx.x;
    for (int i = lane; i < NN; i += 32) ctr[i] = g_ccnt[chunk * NN + i];
    __syncwarp();
    for (int r = 0; r < CE / 32; ++r) {
        int e = chunk * CE + r * 32 + lane;
        int t = tgt[e];
        unsigned mask = __match_any_sync(0xffffffffu, t);
        int leader = __ffs(mask) - 1;
        int rank = __popc(mask & ((1u << lane) - 1u));
        int base = 0;
        if (lane == leader) { base = ctr[t]; ctr[t] = base + __popc(mask); }
        base = __shfl_sync(0xffffffffu, base, leader);
        g_eid[base + rank] = e;
        g_esrc[base + rank] = src[e];
        __syncwarp();
    }
}

// gather edge scalars directly into CSR slot order (run AFTER k_fill)
__global__ void k_ef(const float* __restrict__ edge, const int* __restrict__ src,
                     const int* __restrict__ tgt) {
    int t = blockIdx.x * blockDim.x + threadIdx.x;
    if (t < BB * EE) {
        int b = t / EE, slot = t % EE;
        int e = g_eid[slot];
        g_ef[t] = edge[(size_t)b * NN * NN + (size_t)src[e] * NN + tgt[e]];
    }
}

// ---------------- double-buffered 128x128x16 fp32 GEMM ----------------
// g_big[16384,640] = A[16384,128] @ g_Wbig[128,640] + g_bias1
__global__ __launch_bounds__(256) void k_gemm0(const float* __restrict__ A) {
    constexpr int Nc = 640;
    const float* __restrict__ Bm = g_Wbig;
    const float* __restrict__ bias = g_bias1;
    float* __restrict__ C = g_big;

    __shared__ float As[2][16][132];   // [buf][k][row], padded
    __shared__ float Bs[2][16][128];   // [buf][k][col]

    const int tid = threadIdx.x;
    const int bm = blockIdx.y, bn = blockIdx.x;
    const float* Ab = A + (size_t)bm * 128 * 128;
    const float* Bb = Bm + (size_t)bn * 128;

    const int tx = tid & 15, ty = tid >> 4;

    float4 pa[2], pb[2];

    auto fetch = [&](int k0) {
#pragma unroll
        for (int i = 0; i < 2; ++i) {
            int idx = tid * 2 + i;
            int ar = idx >> 2, akq = idx & 3;          // A: row, k-quad
            pa[i] = *(const float4*)(Ab + (size_t)ar * 128 + k0 + akq * 4);
            int br = idx >> 5, bq = idx & 31;          // B: k-row, n-quad
            pb[i] = *(const float4*)(Bb + (size_t)(k0 + br) * Nc + bq * 4);
        }
    };
    auto store = [&](int buf) {
#pragma unroll
        for (int i = 0; i < 2; ++i) {
            int idx = tid * 2 + i;
            int ar = idx >> 2, akq = idx & 3;
            As[buf][akq * 4 + 0][ar] = pa[i].x;
            As[buf][akq * 4 + 1][ar] = pa[i].y;
            As[buf][akq * 4 + 2][ar] = pa[i].z;
            As[buf][akq * 4 + 3][ar] = pa[i].w;
            int br = idx >> 5, bq = idx & 31;
            *(float4*)&Bs[buf][br][bq * 4] = pb[i];
        }
    };

    float acc[8][8];
#pragma unroll
    for (int i = 0; i < 8; ++i)
#pragma unroll
        for (int j = 0; j < 8; ++j) acc[i][j] = 0.f;

    fetch(0);
    store(0);
    __syncthreads();

#pragma unroll
    for (int s = 0; s < 8; ++s) {
        if (s < 7) fetch((s + 1) * 16);
        int buf = s & 1;
#pragma unroll
        for (int k = 0; k < 16; ++k) {
            float4 a0 = *(const float4*)&As[buf][k][ty * 4];
            float4 a1 = *(const float4*)&As[buf][k][64 + ty * 4];
            float4 b0 = *(const float4*)&Bs[buf][k][tx * 4];
            float4 b1 = *(const float4*)&Bs[buf][k][64 + tx * 4];
            float av[8] = {a0.x, a0.y, a0.z, a0.w, a1.x, a1.y, a1.z, a1.w};
            float bv[8] = {b0.x, b0.y, b0.z, b0.w, b1.x, b1.y, b1.z, b1.w};
#pragma unroll
            for (int i = 0; i < 8; ++i)
#pragma unroll
                for (int j = 0; j < 8; ++j) acc[i][j] = fmaf(av[i], bv[j], acc[i][j]);
        }
        if (s < 7) { store(buf ^ 1); __syncthreads(); }
    }

    int c0 = bn * 128 + tx * 4;
    int c1 = c0 + 64;
    float4 bb0 = {bias[c0], bias[c0 + 1], bias[c0 + 2], bias[c0 + 3]};
    float4 bb1 = {bias[c1], bias[c1 + 1], bias[c1 + 2], bias[c1 + 3]};
#pragma unroll
    for (int i = 0; i < 8; ++i) {
        int row = bm * 128 + ((i < 4) ? (ty * 4 + i) : (64 + ty * 4 + i - 4));
        float4 v0 = {acc[i][0] + bb0.x, acc[i][1] + bb0.y, acc[i][2] + bb0.z, acc[i][3] + bb0.w};
        float4 v1 = {acc[i][4] + bb1.x, acc[i][5] + bb1.y, acc[i][6] + bb1.z, acc[i][7] + bb1.w};
        *(float4*)(C + (size_t)row * Nc + c0) = v0;
        *(float4*)(C + (size_t)row * Nc + c1) = v1;
    }
}

// ---------------- fused edge message + deterministic aggregation ----------------
__global__ __launch_bounds__(128) void k_edge(const float* __restrict__ Wmsg,
                                              const float* __restrict__ bmsg) {
    int lane = threadIdx.x & 31;          // float4 index over D
    int nl = threadIdx.x >> 5;            // node within block
    int n = blockIdx.x * 4 + nl;
    int b = blockIdx.y;
    float4 we = *(const float4*)(Wmsg + 256 * 128 + lane * 4);
    float4 bm = *(const float4*)(bmsg + lane * 4);
    const float* bigb = g_big + (size_t)b * NN * 640;
    float4 ht = *(const float4*)(bigb + (size_t)n * 640 + 128 + lane * 4);
    float4 base = {ht.x + bm.x, ht.y + bm.y, ht.z + bm.z, ht.w + bm.w};
    const float* efb = g_ef + (size_t)b * EE;
    int s0 = g_off[n], s1 = g_off[n + 1];
    float4 acc = {0.f, 0.f, 0.f, 0.f};
    int s = s0;
    for (; s + 2 <= s1; s += 2) {
        int sr0 = g_esrc[s], sr1 = g_esrc[s + 1];
        float e0 = efb[s], e1 = efb[s + 1];
        float4 h0 = *(const float4*)(bigb + (size_t)sr0 * 640 + lane * 4);
        float4 h1 = *(const float4*)(bigb + (size_t)sr1 * 640 + lane * 4);
        acc.x += selu_f(h0.x + base.x + e0 * we.x) + selu_f(h1.x + base.x + e1 * we.x);
        acc.y += selu_f(h0.y + base.y + e0 * we.y) + selu_f(h1.y + base.y + e1 * we.y);
        acc.z += selu_f(h0.z + base.z + e0 * we.z) + selu_f(h1.z + base.z + e1 * we.z);
        acc.w += selu_f(h0.w + base.w + e0 * we.w) + selu_f(h1.w + base.w + e1 * we.w);
    }
    if (s < s1) {
        int sr0 = g_esrc[s];
        float e0 = efb[s];
        float4 h0 = *(const float4*)(bigb + (size_t)sr0 * 640 + lane * 4);
        acc.x += selu_f(h0.x + base.x + e0 * we.x);
        acc.y += selu_f(h0.y + base.y + e0 * we.y);
        acc.z += selu_f(h0.z + base.z + e0 * we.z);
        acc.w += selu_f(h0.w + base.w + e0 * we.w);
    }
    *(float4*)(g_agg + ((size_t)(b * NN + n)) * DD + lane * 4) = acc;
}

// ---------------- fused gemm1 + GRU ----------------
// Per block: 64 rows x 384 cols of gi = g_agg @ g_Wiht + bih, then GRU update
// of g_h in the epilogue (reads hprev for the z*h term; hprev = nf on iter 0).
__global__ __launch_bounds__(256) void k_gemm1_gru(const float* __restrict__ bih,
                                                   const float* __restrict__ hprev) {
    __shared__ float As[2][8][68];    // [buf][k][row]
    __shared__ float Bs[2][8][384];   // [buf][k][col]

    const int tid = threadIdx.x;
    const int bm = blockIdx.x;                  // 64-row panel
    const float* Ab = g_agg + (size_t)bm * 64 * 128;
    const float* Bb = g_Wiht;

    const int tx = tid & 15, ty = tid >> 4;

    float4 pa;       // A: 128 float4 per panel -> tid<128 loads 1
    float4 pb[3];    // B: 768 float4 per panel -> 3 per thread

    auto fetch = [&](int k0) {
        if (tid < 128) {
            int ar = tid >> 1, akq = (tid & 1) * 4;
            pa = *(const float4*)(Ab + (size_t)ar * 128 + k0 + akq);
        }
#pragma unroll
        for (int i = 0; i < 3; ++i) {
            int idx = tid + i * 256;
            int br = idx / 96, bc = (idx % 96) * 4;
            pb[i] = *(const float4*)(Bb + (size_t)(k0 + br) * 384 + bc);
        }
    };
    auto store = [&](int buf) {
        if (tid < 128) {
            int ar = tid >> 1, akq = (tid & 1) * 4;
            As[buf][akq + 0][ar] = pa.x;
            As[buf][akq + 1][ar] = pa.y;
            As[buf][akq + 2][ar] = pa.z;
            As[buf][akq + 3][ar] = pa.w;
        }
#pragma unroll
        for (int i = 0; i < 3; ++i) {
            int idx = tid + i * 256;
            int br = idx / 96, bc = (idx % 96) * 4;
            *(float4*)&Bs[buf][br][bc] = pb[i];
        }
    };

    // acc[row i<4][chunk c<3][col j<8]; cols j<4 -> tx*4+j, j>=4 -> 64+tx*4+j-4
    float acc[4][3][8];
#pragma unroll
    for (int i = 0; i < 4; ++i)
#pragma unroll
        for (int c = 0; c < 3; ++c)
#pragma unroll
            for (int j = 0; j < 8; ++j) acc[i][c][j] = 0.f;

    fetch(0);
    store(0);
    __syncthreads();

#pragma unroll
    for (int s = 0; s < 16; ++s) {
        if (s < 15) fetch((s + 1) * 8);
        int buf = s & 1;
#pragma unroll
        for (int k = 0; k < 8; ++k) {
            float4 a4 = *(const float4*)&As[buf][k][ty * 4];
            float av[4] = {a4.x, a4.y, a4.z, a4.w};
#pragma unroll
            for (int c = 0; c < 3; ++c) {
                float4 b0 = *(const float4*)&Bs[buf][k][c * 128 + tx * 4];
                float4 b1 = *(const float4*)&Bs[buf][k][c * 128 + 64 + tx * 4];
                float bv[8] = {b0.x, b0.y, b0.z, b0.w, b1.x, b1.y, b1.z, b1.w};
#pragma unroll
                for (int i = 0; i < 4; ++i)
#pragma unroll
                    for (int j = 0; j < 8; ++j)
                        acc[i][c][j] = fmaf(av[i], bv[j], acc[i][c][j]);
            }
        }
        if (s < 15) { store(buf ^ 1); __syncthreads(); }
    }

    // bias
    float bi[3][8];
#pragma unroll
    for (int c = 0; c < 3; ++c) {
        float4 u0 = *(const float4*)(bih + c * 128 + tx * 4);
        float4 u1 = *(const float4*)(bih + c * 128 + 64 + tx * 4);
        bi[c][0] = u0.x; bi[c][1] = u0.y; bi[c][2] = u0.z; bi[c][3] = u0.w;
        bi[c][4] = u1.x; bi[c][5] = u1.y; bi[c][6] = u1.z; bi[c][7] = u1.w;
    }

    // GRU epilogue: each thread handles 4 rows x 8 cols (2 float4 groups)
#pragma unroll
    for (int i = 0; i < 4; ++i) {
        int row = bm * 64 + ty * 4 + i;
        const float* gh = g_big + (size_t)row * 640 + 256;
        const float* hp = hprev + (size_t)row * 128;
        float* ho = g_h + (size_t)row * 128;
#pragma unroll
        for (int g = 0; g < 2; ++g) {          // col group: base or +64
            int c0 = g * 64 + tx * 4;
            float4 hr = *(const float4*)(gh + c0);
            float4 hz = *(const float4*)(gh + 128 + c0);
            float4 hn = *(const float4*)(gh + 256 + c0);
            float4 hv = *(const float4*)(hp + c0);
            float4 outv;
            float* hrp = (float*)&hr; float* hzp = (float*)&hz;
            float* hnp = (float*)&hn; float* hvp = (float*)&hv;
            float* op = (float*)&outv;
#pragma unroll
            for (int j = 0; j < 4; ++j) {
                int jj = g * 4 + j;
                float ir = acc[i][0][jj] + bi[0][jj];
                float iz = acc[i][1][jj] + bi[1][jj];
                float in_ = acc[i][2][jj] + bi[2][jj];
                float r = 1.f / (1.f + __expf(-(ir + hrp[j])));
                float z = 1.f / (1.f + __expf(-(iz + hzp[j])));
                float nv = tanhf(in_ + r * hnp[j]);
                op[j] = (1.f - z) * nv + z * hvp[j];
            }
            *(float4*)(ho + c0) = outv;
        }
    }
}

// ---------------- pooling + readout head ----------------
__global__ void k_pool() {  // grid (16 chunks, B), 128 threads
    int c = blockIdx.x, b = blockIdx.y, d = threadIdx.x;
    const float* hb = g_h + ((size_t)b * NN + c * 64) * DD + d;
    float s = 0.f;
#pragma unroll 8
    for (int n = 0; n < 64; ++n) s += hb[(size_t)n * DD];
    g_part[(b * 16 + c) * DD + d] = s;
}

__global__ void k_head(const float* __restrict__ Wr1, const float* __restrict__ br1,
                       const float* __restrict__ Wr2, const float* __restrict__ br2,
                       const float* __restrict__ Wpol, const float* __restrict__ bpol,
                       float* __restrict__ out) {
    int b = blockIdx.x, d = threadIdx.x;  // 128 threads
    __shared__ float p[128], q[128];
    float s = 0.f;
#pragma unroll
    for (int c = 0; c < 16; ++c) s += g_part[(b * 16 + c) * DD + d];
    p[d] = s;
    __syncthreads();
    float y = br1[d];
#pragma unroll 8
    for (int k = 0; k < 128; ++k) y = fmaf(p[k], Wr1[k * 128 + d], y);
    q[d] = selu_f(y);
    __syncthreads();
    y = br2[d];
#pragma unroll 8
    for (int k = 0; k < 128; ++k) y = fmaf(q[k], Wr2[k * 128 + d], y);
    float p2 = selu_f(y);
    __syncthreads();
    p[d] = p2;
    __syncthreads();
    if (d < 64) {
        float o = bpol[d];
#pragma unroll 8
        for (int k = 0; k < 128; ++k) o = fmaf(p[k], Wpol[k * 64 + d], o);
        out[b * 64 + d] = o;
    }
}

// ---------------- launch ----------------
extern "C" void kernel_launch(void* const* d_in, const int* in_sizes, int n_in,
                              void* d_out, int out_size) {
    const float* nf   = (const float*)d_in[0];
    const float* edge = (const float*)d_in[1];
    const int*   src  = (const int*)d_in[2];
    const int*   tgt  = (const int*)d_in[3];
    const float* Wmsg = (const float*)d_in[4];
    const float* bmsg = (const float*)d_in[5];
    const float* Wih  = (const float*)d_in[6];
    const float* Whh  = (const float*)d_in[7];
    const float* bih  = (const float*)d_in[8];
    const float* bhh  = (const float*)d_in[9];
    const float* Wr1  = (const float*)d_in[10];
    const float* br1  = (const float*)d_in[11];
    const float* Wr2  = (const float*)d_in[12];
    const float* br2  = (const float*)d_in[13];
    const float* Wpol = (const float*)d_in[14];
    const float* bpol = (const float*)d_in[15];
    float* out = (float*)d_out;

    float* g_h_ptr = nullptr;
    cudaGetSymbolAddress((void**)&g_h_ptr, g_h);

    // launch index 3 == first k_gemm0 (profiled by ncu -s 5 -c 1)
    k_pack<<<(128 * 640 + 255) / 256, 256>>>(Wmsg, Whh, bhh, Wih);
    k_cnt<<<CH, 256>>>(tgt);
    k_tot<<<8, 128>>>();
    k_gemm0<<<dim3(5, 128), 256>>>(nf);           // iter-0 gemm0 reads nf directly
    k_scanx<<<1, NN>>>();
    k_offk<<<8, 128>>>();
    k_fill<<<CH, 32>>>(tgt, src);
    k_ef<<<(BB * EE + 255) / 256, 256>>>(edge, src, tgt);

    for (int it = 0; it < DIAM; ++it) {
        if (it > 0) k_gemm0<<<dim3(5, 128), 256>>>(g_h_ptr);
        k_edge<<<dim3(NN / 4, BB), 128>>>(Wmsg, bmsg);
        k_gemm1_gru<<<256, 256>>>(bih, it == 0 ? nf : g_h_ptr);
    }

    k_pool<<<dim3(16, BB), 128>>>();
    k_head<<<BB, 128>>>(Wr1, br1, Wr2, br2, Wpol, bpol, out);
}

// round 4
// speedup vs baseline: 1.8409x; 1.8409x over previous
#include <cuda_runtime.h>
#include <cuda_bf16.h>
#include <cstdint>

// Problem constants
#define BB   16
#define NN   1024
#define DD   128
#define EE   16384
#define AA   64
#define DIAM 3
#define CH   64           // edge chunks for CSR build
#define CE   (EE / CH)    // 256 edges per chunk

// ---------------- device scratch (no allocations allowed) ----------------
__device__ float g_h[BB * NN * DD];            // node state
__device__ float g_big[BB * NN * 640];         // [hs|ht|gh] per node
__device__ float g_agg[BB * NN * DD];          // aggregated messages
__device__ float g_gi[BB * NN * 384];          // gi = agg@Wih^T
__device__ float g_ef[BB * EE];                // edge scalars, CSR slot order
__device__ __nv_bfloat16 g_Wbh[640 * 128];     // packed big weight, hi, [n][k]
__device__ __nv_bfloat16 g_Wbl[640 * 128];     // lo
__device__ __nv_bfloat16 g_Wih_h[384 * 128];   // W_ih hi, [n][k]
__device__ __nv_bfloat16 g_Wih_l[384 * 128];   // lo
__device__ float g_bias1[640];                 // [0,0,b_hh]
__device__ int   g_ccnt[CH * NN];
__device__ int   g_deg[NN];
__device__ int   g_off[NN + 1];
__device__ int   g_eid[EE];
__device__ int   g_esrc[EE];
__device__ float g_part[BB * 16 * DD];

__device__ __forceinline__ float selu_f(float x) {
    const float sc = 1.0507009873554805f, al = 1.6732632423543772f;
    return x > 0.f ? sc * x : sc * al * (__expf(x) - 1.f);
}

// ---------------- setup kernels ----------------
__global__ void k_pack(const float* __restrict__ Wmsg, const float* __restrict__ Whh,
                       const float* __restrict__ bhh, const float* __restrict__ Wih) {
    int t = blockIdx.x * blockDim.x + threadIdx.x;
    if (t < 640 * 128) {
        int n = t >> 7, k = t & 127;
        float v;
        if (n < 128)       v = Wmsg[k * 128 + n];                 // src part
        else if (n < 256)  v = Wmsg[(128 + k) * 128 + (n - 128)]; // tgt part
        else               v = Whh[(n - 256) * 128 + k];          // W_hh^T
        __nv_bfloat16 hi = __float2bfloat16(v);
        g_Wbh[t] = hi;
        g_Wbl[t] = __float2bfloat16(v - __bfloat162float(hi));
    }
    if (t < 384 * 128) {
        float v = Wih[t];  // Wih is [384][128] row-major == [n][k]
        __nv_bfloat16 hi = __float2bfloat16(v);
        g_Wih_h[t] = hi;
        g_Wih_l[t] = __float2bfloat16(v - __bfloat162float(hi));
    }
    if (t < 640) g_bias1[t] = (t < 256) ? 0.f : bhh[t - 256];
}

// ---- CSR build: chunked histogram (deterministic stable order) ----
__global__ void k_cnt(const int* __restrict__ tgt) {  // grid CH, block 256
    __shared__ int c[NN];
    for (int i = threadIdx.x; i < NN; i += 256) c[i] = 0;
    __syncthreads();
    int e = blockIdx.x * CE + threadIdx.x;
    atomicAdd(&c[tgt[e]], 1);
    __syncthreads();
    for (int i = threadIdx.x; i < NN; i += 256) g_ccnt[blockIdx.x * NN + i] = c[i];
}

__global__ void k_tot() {  // grid 8, block 128
    int n = blockIdx.x * 128 + threadIdx.x;
    int s = 0;
#pragma unroll
    for (int c = 0; c < CH; ++c) s += g_ccnt[c * NN + n];
    g_deg[n] = s;
}

__global__ void k_scanx() {  // 1 block, 1024 threads
    __shared__ int s[NN];
    int n = threadIdx.x;
    s[n] = g_deg[n];
    __syncthreads();
    for (int o = 1; o < NN; o <<= 1) {
        int x = (n >= o) ? s[n - o] : 0;
        __syncthreads();
        s[n] += x;
        __syncthreads();
    }
    g_off[n + 1] = s[n];
    if (n == 0) g_off[0] = 0;
}

__global__ void k_offk() {  // grid 8, block 128
    int n = blockIdx.x * 128 + threadIdx.x;
    int run = g_off[n];
#pragma unroll
    for (int c = 0; c < CH; ++c) {
        int v = g_ccnt[c * NN + n];
        g_ccnt[c * NN + n] = run;
        run += v;
    }
}

__global__ void k_fill(const int* __restrict__ tgt, const int* __restrict__ src) {
    __shared__ int ctr[NN];
    int lane = threadIdx.x;
    int chunk = blockIdx.x;
    for (int i = lane; i < NN; i += 32) ctr[i] = g_ccnt[chunk * NN + i];
    __syncwarp();
    for (int r = 0; r < CE / 32; ++r) {
        int e = chunk * CE + r * 32 + lane;
        int t = tgt[e];
        unsigned mask = __match_any_sync(0xffffffffu, t);
        int leader = __ffs(mask) - 1;
        int rank = __popc(mask & ((1u << lane) - 1u));
        int base = 0;
        if (lane == leader) { base = ctr[t]; ctr[t] = base + __popc(mask); }
        base = __shfl_sync(0xffffffffu, base, leader);
        g_eid[base + rank] = e;
        g_esrc[base + rank] = src[e];
        __syncwarp();
    }
}

__global__ void k_ef(const float* __restrict__ edge, const int* __restrict__ src,
                     const int* __restrict__ tgt) {
    int t = blockIdx.x * blockDim.x + threadIdx.x;
    if (t < BB * EE) {
        int b = t / EE, slot = t % EE;
        int e = g_eid[slot];
        g_ef[t] = edge[(size_t)b * NN * NN + (size_t)src[e] * NN + tgt[e]];
    }
}

// ---------------- split-bf16 tensor-core GEMM ----------------
// C[16384, Nc] = A[16384,128] @ W[128,Nc] + bias   via  Ah·Bh + Ah·Bl + Al·Bh
// Block: 128 rows x 128 cols, whole K in smem. 8 warps: 2(m) x 4(n), warp tile 64x32.
#define SROW 136                     // padded row in bf16 elems (272B: conflict-free ldmatrix)
#define A_H 0
#define A_L (128 * SROW)
#define B_H (2 * 128 * SROW)
#define B_L (3 * 128 * SROW)
#define MM_SMEM (4 * 128 * SROW * 2) // bytes = 139264

__device__ __forceinline__ void ldsm4(uint32_t& r0, uint32_t& r1, uint32_t& r2, uint32_t& r3,
                                      uint32_t addr) {
    asm volatile("ldmatrix.sync.aligned.m8n8.x4.shared.b16 {%0,%1,%2,%3},[%4];"
                 : "=r"(r0), "=r"(r1), "=r"(r2), "=r"(r3) : "r"(addr));
}
__device__ __forceinline__ void mma_bf16(float* d, const uint32_t* a, const uint32_t* b) {
    asm volatile(
        "mma.sync.aligned.m16n8k16.row.col.f32.bf16.bf16.f32 "
        "{%0,%1,%2,%3},{%4,%5,%6,%7},{%8,%9},{%0,%1,%2,%3};"
        : "+f"(d[0]), "+f"(d[1]), "+f"(d[2]), "+f"(d[3])
        : "r"(a[0]), "r"(a[1]), "r"(a[2]), "r"(a[3]), "r"(b[0]), "r"(b[1]));
}

template <int Nc>
__global__ __launch_bounds__(256) void k_mm(const float* __restrict__ A,
                                            const __nv_bfloat16* __restrict__ Bhg,
                                            const __nv_bfloat16* __restrict__ Blg,
                                            const float* __restrict__ bias,
                                            float* __restrict__ C) {
    extern __shared__ char smraw[];
    __nv_bfloat16* sm = (__nv_bfloat16*)smraw;
    const int tid = threadIdx.x;
    const int bn = blockIdx.x, bm = blockIdx.y;
    const int lane = tid & 31, w = tid >> 5;
    const int wm = w >> 2, wn = w & 3;       // warp grid 2 x 4

    // ---- load A (fp32 -> bf16 hi/lo) ----
    for (int i = tid; i < 2048; i += 256) {
        int row = i >> 4, c = i & 15;
        const float* ap = A + ((size_t)(bm * 128 + row)) * 128 + c * 8;
        float4 v0 = *(const float4*)ap;
        float4 v1 = *(const float4*)(ap + 4);
        float v[8] = {v0.x, v0.y, v0.z, v0.w, v1.x, v1.y, v1.z, v1.w};
        __nv_bfloat162 hx[4], lx[4];
#pragma unroll
        for (int j = 0; j < 4; ++j) {
            __nv_bfloat16 h0 = __float2bfloat16(v[2 * j]);
            __nv_bfloat16 h1 = __float2bfloat16(v[2 * j + 1]);
            hx[j] = __nv_bfloat162(h0, h1);
            lx[j] = __nv_bfloat162(__float2bfloat16(v[2 * j] - __bfloat162float(h0)),
                                   __float2bfloat16(v[2 * j + 1] - __bfloat162float(h1)));
        }
        int off = row * SROW + c * 8;
        *(uint4*)&sm[A_H + off] = *(uint4*)hx;
        *(uint4*)&sm[A_L + off] = *(uint4*)lx;
    }
    // ---- load B (bf16 copy) ----
    for (int i = tid; i < 2048; i += 256) {
        int row = i >> 4, c = i & 15;
        size_t g = ((size_t)(bn * 128 + row)) * 128 + c * 8;
        int off = row * SROW + c * 8;
        *(uint4*)&sm[B_H + off] = *(const uint4*)(Bhg + g);
        *(uint4*)&sm[B_L + off] = *(const uint4*)(Blg + g);
    }
    __syncthreads();

    uint32_t sbase = (uint32_t)__cvta_generic_to_shared(smraw);

    float acc[4][4][4];
#pragma unroll
    for (int mt = 0; mt < 4; ++mt)
#pragma unroll
        for (int nt = 0; nt < 4; ++nt)
#pragma unroll
            for (int q = 0; q < 4; ++q) acc[mt][nt][q] = 0.f;

    const int arow = wm * 64 + (lane & 15);
    const int akof = (lane >> 4) << 3;
    const int bnrow = wn * 32 + ((lane >> 4) << 3) + (lane & 7);
    const int bkof = ((lane >> 3) & 1) << 3;

#pragma unroll 1
    for (int ks = 0; ks < 8; ++ks) {
        int k0 = ks * 16;
        uint32_t ah[4][4], al[4][4], bh[2][4], bl[2][4];
#pragma unroll
        for (int mt = 0; mt < 4; ++mt) {
            uint32_t off = (uint32_t)((arow + mt * 16) * SROW + k0 + akof) * 2;
            ldsm4(ah[mt][0], ah[mt][1], ah[mt][2], ah[mt][3], sbase + A_H * 2 + off);
            ldsm4(al[mt][0], al[mt][1], al[mt][2], al[mt][3], sbase + A_L * 2 + off);
        }
#pragma unroll
        for (int np = 0; np < 2; ++np) {
            uint32_t off = (uint32_t)((bnrow + np * 16) * SROW + k0 + bkof) * 2;
            ldsm4(bh[np][0], bh[np][1], bh[np][2], bh[np][3], sbase + B_H * 2 + off);
            ldsm4(bl[np][0], bl[np][1], bl[np][2], bl[np][3], sbase + B_L * 2 + off);
        }
#pragma unroll
        for (int mt = 0; mt < 4; ++mt)
#pragma unroll
            for (int nt = 0; nt < 4; ++nt) {
                const uint32_t* bhp = &bh[nt >> 1][(nt & 1) * 2];
                const uint32_t* blp = &bl[nt >> 1][(nt & 1) * 2];
                mma_bf16(acc[mt][nt], ah[mt], bhp);
                mma_bf16(acc[mt][nt], ah[mt], blp);
                mma_bf16(acc[mt][nt], al[mt], bhp);
            }
    }

    // ---- epilogue ----
    const int grp = lane >> 2, qp = lane & 3;
    float2 bv[4];
#pragma unroll
    for (int nt = 0; nt < 4; ++nt) {
        int col = bn * 128 + wn * 32 + nt * 8 + qp * 2;
        bv[nt] = *(const float2*)(bias + col);
    }
#pragma unroll
    for (int mt = 0; mt < 4; ++mt) {
        int row = bm * 128 + wm * 64 + mt * 16 + grp;
#pragma unroll
        for (int nt = 0; nt < 4; ++nt) {
            int col = bn * 128 + wn * 32 + nt * 8 + qp * 2;
            float2 v0 = {acc[mt][nt][0] + bv[nt].x, acc[mt][nt][1] + bv[nt].y};
            float2 v1 = {acc[mt][nt][2] + bv[nt].x, acc[mt][nt][3] + bv[nt].y};
            *(float2*)(C + (size_t)row * Nc + col) = v0;
            *(float2*)(C + (size_t)(row + 8) * Nc + col) = v1;
        }
    }
}

// ---------------- fused edge message + deterministic aggregation ----------------
__global__ __launch_bounds__(128) void k_edge(const float* __restrict__ Wmsg,
                                              const float* __restrict__ bmsg) {
    int lane = threadIdx.x & 31;
    int nl = threadIdx.x >> 5;
    int n = blockIdx.x * 4 + nl;
    int b = blockIdx.y;
    float4 we = *(const float4*)(Wmsg + 256 * 128 + lane * 4);
    float4 bm = *(const float4*)(bmsg + lane * 4);
    const float* bigb = g_big + (size_t)b * NN * 640;
    float4 ht = *(const float4*)(bigb + (size_t)n * 640 + 128 + lane * 4);
    float4 base = {ht.x + bm.x, ht.y + bm.y, ht.z + bm.z, ht.w + bm.w};
    const float* efb = g_ef + (size_t)b * EE;
    int s0 = g_off[n], s1 = g_off[n + 1];
    float4 acc = {0.f, 0.f, 0.f, 0.f};
    int s = s0;
    for (; s + 2 <= s1; s += 2) {
        int sr0 = g_esrc[s], sr1 = g_esrc[s + 1];
        float e0 = efb[s], e1 = efb[s + 1];
        float4 h0 = *(const float4*)(bigb + (size_t)sr0 * 640 + lane * 4);
        float4 h1 = *(const float4*)(bigb + (size_t)sr1 * 640 + lane * 4);
        acc.x += selu_f(h0.x + base.x + e0 * we.x) + selu_f(h1.x + base.x + e1 * we.x);
        acc.y += selu_f(h0.y + base.y + e0 * we.y) + selu_f(h1.y + base.y + e1 * we.y);
        acc.z += selu_f(h0.z + base.z + e0 * we.z) + selu_f(h1.z + base.z + e1 * we.z);
        acc.w += selu_f(h0.w + base.w + e0 * we.w) + selu_f(h1.w + base.w + e1 * we.w);
    }
    if (s < s1) {
        int sr0 = g_esrc[s];
        float e0 = efb[s];
        float4 h0 = *(const float4*)(bigb + (size_t)sr0 * 640 + lane * 4);
        acc.x += selu_f(h0.x + base.x + e0 * we.x);
        acc.y += selu_f(h0.y + base.y + e0 * we.y);
        acc.z += selu_f(h0.z + base.z + e0 * we.z);
        acc.w += selu_f(h0.w + base.w + e0 * we.w);
    }
    *(float4*)(g_agg + ((size_t)(b * NN + n)) * DD + lane * 4) = acc;
}

// ---------------- GRU elementwise ----------------
__global__ void k_gru(const float* __restrict__ hprev) {
    int t = blockIdx.x * blockDim.x + threadIdx.x;
    if (t >= BB * NN * DD) return;
    int row = t >> 7, d = t & 127;
    const float* gi = g_gi + (size_t)row * 384;
    const float* gh = g_big + (size_t)row * 640 + 256;
    float ir = gi[d], iz = gi[128 + d], in_ = gi[256 + d];
    float hr = gh[d], hz = gh[128 + d], hn = gh[256 + d];
    float h = hprev[t];
    float r = 1.f / (1.f + __expf(-(ir + hr)));
    float z = 1.f / (1.f + __expf(-(iz + hz)));
    float nv = tanhf(in_ + r * hn);
    g_h[t] = (1.f - z) * nv + z * h;
}

// ---------------- pooling + readout head ----------------
__global__ void k_pool() {
    int c = blockIdx.x, b = blockIdx.y, d = threadIdx.x;
    const float* hb = g_h + ((size_t)b * NN + c * 64) * DD + d;
    float s = 0.f;
#pragma unroll 8
    for (int n = 0; n < 64; ++n) s += hb[(size_t)n * DD];
    g_part[(b * 16 + c) * DD + d] = s;
}

__global__ void k_head(const float* __restrict__ Wr1, const float* __restrict__ br1,
                       const float* __restrict__ Wr2, const float* __restrict__ br2,
                       const float* __restrict__ Wpol, const float* __restrict__ bpol,
                       float* __restrict__ out) {
    int b = blockIdx.x, d = threadIdx.x;
    __shared__ float p[128], q[128];
    float s = 0.f;
#pragma unroll
    for (int c = 0; c < 16; ++c) s += g_part[(b * 16 + c) * DD + d];
    p[d] = s;
    __syncthreads();
    float y = br1[d];
#pragma unroll 8
    for (int k = 0; k < 128; ++k) y = fmaf(p[k], Wr1[k * 128 + d], y);
    q[d] = selu_f(y);
    __syncthreads();
    y = br2[d];
#pragma unroll 8
    for (int k = 0; k < 128; ++k) y = fmaf(q[k], Wr2[k * 128 + d], y);
    float p2 = selu_f(y);
    __syncthreads();
    p[d] = p2;
    __syncthreads();
    if (d < 64) {
        float o = bpol[d];
#pragma unroll 8
        for (int k = 0; k < 128; ++k) o = fmaf(p[k], Wpol[k * 64 + d], o);
        out[b * 64 + d] = o;
    }
}

// ---------------- launch ----------------
extern "C" void kernel_launch(void* const* d_in, const int* in_sizes, int n_in,
                              void* d_out, int out_size) {
    const float* nf   = (const float*)d_in[0];
    const float* edge = (const float*)d_in[1];
    const int*   src  = (const int*)d_in[2];
    const int*   tgt  = (const int*)d_in[3];
    const float* Wmsg = (const float*)d_in[4];
    const float* bmsg = (const float*)d_in[5];
    const float* Wih  = (const float*)d_in[6];
    const float* Whh  = (const float*)d_in[7];
    const float* bih  = (const float*)d_in[8];
    const float* bhh  = (const float*)d_in[9];
    const float* Wr1  = (const float*)d_in[10];
    const float* br1  = (const float*)d_in[11];
    const float* Wr2  = (const float*)d_in[12];
    const float* br2  = (const float*)d_in[13];
    const float* Wpol = (const float*)d_in[14];
    const float* bpol = (const float*)d_in[15];
    float* out = (float*)d_out;

    float *g_h_p, *g_big_p, *g_gi_p, *g_bias1_p;
    __nv_bfloat16 *wbh_p, *wbl_p, *wih_h_p, *wih_l_p;
    cudaGetSymbolAddress((void**)&g_h_p, g_h);
    cudaGetSymbolAddress((void**)&g_big_p, g_big);
    cudaGetSymbolAddress((void**)&g_gi_p, g_gi);
    cudaGetSymbolAddress((void**)&g_bias1_p, g_bias1);
    cudaGetSymbolAddress((void**)&wbh_p, g_Wbh);
    cudaGetSymbolAddress((void**)&wbl_p, g_Wbl);
    cudaGetSymbolAddress((void**)&wih_h_p, g_Wih_h);
    cudaGetSymbolAddress((void**)&wih_l_p, g_Wih_l);

    cudaFuncSetAttribute(k_mm<640>, cudaFuncAttributeMaxDynamicSharedMemorySize, MM_SMEM);
    cudaFuncSetAttribute(k_mm<384>, cudaFuncAttributeMaxDynamicSharedMemorySize, MM_SMEM);
    float* agg_p;
    cudaGetSymbolAddress((void**)&agg_p, g_agg);

    // launch index 3 == first k_mm<640> (profiled)
    k_pack<<<320, 256>>>(Wmsg, Whh, bhh, Wih);
    k_cnt<<<CH, 256>>>(tgt);
    k_tot<<<8, 128>>>();
    k_mm<640><<<dim3(5, 128), 256, MM_SMEM>>>(nf, wbh_p, wbl_p, g_bias1_p, g_big_p);
    k_scanx<<<1, NN>>>();
    k_offk<<<8, 128>>>();
    k_fill<<<CH, 32>>>(tgt, src);
    k_ef<<<(BB * EE + 255) / 256, 256>>>(edge, src, tgt);

    for (int it = 0; it < DIAM; ++it) {
        if (it > 0)
            k_mm<640><<<dim3(5, 128), 256, MM_SMEM>>>(g_h_p, wbh_p, wbl_p, g_bias1_p, g_big_p);
        k_edge<<<dim3(NN / 4, BB), 128>>>(Wmsg, bmsg);
        k_mm<384><<<dim3(3, 128), 256, MM_SMEM>>>(agg_p, wih_h_p, wih_l_p, bih, g_gi_p);
        k_gru<<<(BB * NN * DD + 255) / 256, 256>>>(it == 0 ? nf : g_h_p);
    }

    k_pool<<<dim3(16, BB), 128>>>();
    k_head<<<BB, 128>>>(Wr1, br1, Wr2, br2, Wpol, bpol, out);
}

// round 5
// speedup vs baseline: 2.1675x; 1.1774x over previous
#include <cuda_runtime.h>
#include <cuda_bf16.h>
#include <cstdint>

// Problem constants
#define BB   16
#define NN   1024
#define DD   128
#define EE   16384
#define AA   64
#define DIAM 3
#define CH   64           // edge chunks for CSR build
#define CE   (EE / CH)    // 256 edges per chunk

// ---------------- device scratch (no allocations allowed) ----------------
__device__ float g_h[BB * NN * DD];            // node state
__device__ float g_big[BB * NN * 640];         // [hs|ht|gh] per node
__device__ float g_agg[BB * NN * DD];          // aggregated messages
__device__ float g_gi[BB * NN * 384];          // gi = agg@Wih^T
__device__ float g_ef[BB * EE];                // edge scalars, CSR slot order
__device__ __nv_bfloat16 g_Wbh[640 * 128];     // packed big weight, hi, [n][k]
__device__ __nv_bfloat16 g_Wbl[640 * 128];     // lo
__device__ __nv_bfloat16 g_Wih_h[384 * 128];   // W_ih hi, [n][k]
__device__ __nv_bfloat16 g_Wih_l[384 * 128];   // lo
__device__ float g_bias1[640];                 // [0,0,b_hh]
__device__ int   g_ccnt[CH * NN];
__device__ int   g_deg[NN];
__device__ int   g_off[NN + 1];
__device__ int   g_eid[EE];
__device__ int   g_esrc[EE];
__device__ float g_part[BB * 16 * DD];

__device__ __forceinline__ float selu_f(float x) {
    const float sc = 1.0507009873554805f, al = 1.6732632423543772f;
    return x > 0.f ? sc * x : sc * al * (__expf(x) - 1.f);
}

// ---------------- setup kernels ----------------
__global__ void k_pack(const float* __restrict__ Wmsg, const float* __restrict__ Whh,
                       const float* __restrict__ bhh, const float* __restrict__ Wih) {
    int t = blockIdx.x * blockDim.x + threadIdx.x;
    if (t < 640 * 128) {
        int n = t >> 7, k = t & 127;
        float v;
        if (n < 128)       v = Wmsg[k * 128 + n];                 // src part
        else if (n < 256)  v = Wmsg[(128 + k) * 128 + (n - 128)]; // tgt part
        else               v = Whh[(n - 256) * 128 + k];          // W_hh^T
        __nv_bfloat16 hi = __float2bfloat16(v);
        g_Wbh[t] = hi;
        g_Wbl[t] = __float2bfloat16(v - __bfloat162float(hi));
    }
    if (t < 384 * 128) {
        float v = Wih[t];  // Wih is [384][128] row-major == [n][k]
        __nv_bfloat16 hi = __float2bfloat16(v);
        g_Wih_h[t] = hi;
        g_Wih_l[t] = __float2bfloat16(v - __bfloat162float(hi));
    }
    if (t < 640) g_bias1[t] = (t < 256) ? 0.f : bhh[t - 256];
}

// ---- CSR build: chunked histogram (deterministic stable order) ----
__global__ void k_cnt(const int* __restrict__ tgt) {  // grid CH, block 256
    __shared__ int c[NN];
    for (int i = threadIdx.x; i < NN; i += 256) c[i] = 0;
    __syncthreads();
    int e = blockIdx.x * CE + threadIdx.x;
    atomicAdd(&c[tgt[e]], 1);
    __syncthreads();
    for (int i = threadIdx.x; i < NN; i += 256) g_ccnt[blockIdx.x * NN + i] = c[i];
}

__global__ void k_tot() {  // grid 8, block 128
    int n = blockIdx.x * 128 + threadIdx.x;
    int s = 0;
#pragma unroll
    for (int c = 0; c < CH; ++c) s += g_ccnt[c * NN + n];
    g_deg[n] = s;
}

__global__ void k_scanx() {  // 1 block, 1024 threads
    __shared__ int s[NN];
    int n = threadIdx.x;
    s[n] = g_deg[n];
    __syncthreads();
    for (int o = 1; o < NN; o <<= 1) {
        int x = (n >= o) ? s[n - o] : 0;
        __syncthreads();
        s[n] += x;
        __syncthreads();
    }
    g_off[n + 1] = s[n];
    if (n == 0) g_off[0] = 0;
}

__global__ void k_offk() {  // grid 8, block 128
    int n = blockIdx.x * 128 + threadIdx.x;
    int run = g_off[n];
#pragma unroll
    for (int c = 0; c < CH; ++c) {
        int v = g_ccnt[c * NN + n];
        g_ccnt[c * NN + n] = run;
        run += v;
    }
}

__global__ void k_fill(const int* __restrict__ tgt, const int* __restrict__ src) {
    __shared__ int ctr[NN];
    int lane = threadIdx.x;
    int chunk = blockIdx.x;
    for (int i = lane; i < NN; i += 32) ctr[i] = g_ccnt[chunk * NN + i];
    __syncwarp();
    for (int r = 0; r < CE / 32; ++r) {
        int e = chunk * CE + r * 32 + lane;
        int t = tgt[e];
        unsigned mask = __match_any_sync(0xffffffffu, t);
        int leader = __ffs(mask) - 1;
        int rank = __popc(mask & ((1u << lane) - 1u));
        int base = 0;
        if (lane == leader) { base = ctr[t]; ctr[t] = base + __popc(mask); }
        base = __shfl_sync(0xffffffffu, base, leader);
        g_eid[base + rank] = e;
        g_esrc[base + rank] = src[e];
        __syncwarp();
    }
}

__global__ void k_ef(const float* __restrict__ edge, const int* __restrict__ src,
                     const int* __restrict__ tgt) {
    int t = blockIdx.x * blockDim.x + threadIdx.x;
    if (t < BB * EE) {
        int b = t / EE, slot = t % EE;
        int e = g_eid[slot];
        g_ef[t] = edge[(size_t)b * NN * NN + (size_t)src[e] * NN + tgt[e]];
    }
}

// ---------------- split-bf16 tensor-core GEMM (64-row tiles, 2 blocks/SM) ----------------
// C[16384, Nc] = A[16384,128] @ W[128,Nc] + bias   via  Ah·Bh + Ah·Bl + Al·Bh
// Block: 64 rows x 128 cols, whole K in smem. 8 warps: 2(m) x 4(n), warp tile 32x32.
#define SROW 136                     // padded row in bf16 elems (conflict-free ldmatrix)
#define A_H 0
#define A_L (64 * SROW)
#define B_H (2 * 64 * SROW)
#define B_L (2 * 64 * SROW + 128 * SROW)
#define MM_SMEM ((2 * 64 + 2 * 128) * SROW * 2)   // 104448 bytes -> 2 blocks/SM

__device__ __forceinline__ void ldsm4(uint32_t& r0, uint32_t& r1, uint32_t& r2, uint32_t& r3,
                                      uint32_t addr) {
    asm volatile("ldmatrix.sync.aligned.m8n8.x4.shared.b16 {%0,%1,%2,%3},[%4];"
                 : "=r"(r0), "=r"(r1), "=r"(r2), "=r"(r3) : "r"(addr));
}
__device__ __forceinline__ void mma_bf16(float* d, const uint32_t* a, const uint32_t* b) {
    asm volatile(
        "mma.sync.aligned.m16n8k16.row.col.f32.bf16.bf16.f32 "
        "{%0,%1,%2,%3},{%4,%5,%6,%7},{%8,%9},{%0,%1,%2,%3};"
        : "+f"(d[0]), "+f"(d[1]), "+f"(d[2]), "+f"(d[3])
        : "r"(a[0]), "r"(a[1]), "r"(a[2]), "r"(a[3]), "r"(b[0]), "r"(b[1]));
}

template <int Nc>
__global__ __launch_bounds__(256) void k_mm(const float* __restrict__ A,
                                            const __nv_bfloat16* __restrict__ Bhg,
                                            const __nv_bfloat16* __restrict__ Blg,
                                            const float* __restrict__ bias,
                                            float* __restrict__ C) {
    extern __shared__ char smraw[];
    __nv_bfloat16* sm = (__nv_bfloat16*)smraw;
    const int tid = threadIdx.x;
    const int bn = blockIdx.x, bm = blockIdx.y;
    const int lane = tid & 31, w = tid >> 5;
    const int wm = w >> 2, wn = w & 3;       // warp grid 2 x 4

    // ---- load A: 64 rows (fp32 -> bf16 hi/lo) ----
    for (int i = tid; i < 1024; i += 256) {
        int row = i >> 4, c = i & 15;
        const float* ap = A + ((size_t)(bm * 64 + row)) * 128 + c * 8;
        float4 v0 = *(const float4*)ap;
        float4 v1 = *(const float4*)(ap + 4);
        float v[8] = {v0.x, v0.y, v0.z, v0.w, v1.x, v1.y, v1.z, v1.w};
        __nv_bfloat162 hx[4], lx[4];
#pragma unroll
        for (int j = 0; j < 4; ++j) {
            __nv_bfloat16 h0 = __float2bfloat16(v[2 * j]);
            __nv_bfloat16 h1 = __float2bfloat16(v[2 * j + 1]);
            hx[j] = __nv_bfloat162(h0, h1);
            lx[j] = __nv_bfloat162(__float2bfloat16(v[2 * j] - __bfloat162float(h0)),
                                   __float2bfloat16(v[2 * j + 1] - __bfloat162float(h1)));
        }
        int off = row * SROW + c * 8;
        *(uint4*)&sm[A_H + off] = *(uint4*)hx;
        *(uint4*)&sm[A_L + off] = *(uint4*)lx;
    }
    // ---- load B: 128 cols (bf16 copy) ----
    for (int i = tid; i < 2048; i += 256) {
        int row = i >> 4, c = i & 15;
        size_t g = ((size_t)(bn * 128 + row)) * 128 + c * 8;
        int off = row * SROW + c * 8;
        *(uint4*)&sm[B_H + off] = *(const uint4*)(Bhg + g);
        *(uint4*)&sm[B_L + off] = *(const uint4*)(Blg + g);
    }
    __syncthreads();

    uint32_t sbase = (uint32_t)__cvta_generic_to_shared(smraw);

    float acc[2][4][4];
#pragma unroll
    for (int mt = 0; mt < 2; ++mt)
#pragma unroll
        for (int nt = 0; nt < 4; ++nt)
#pragma unroll
            for (int q = 0; q < 4; ++q) acc[mt][nt][q] = 0.f;

    const int arow = wm * 32 + (lane & 15);
    const int akof = (lane >> 4) << 3;
    const int bnrow = wn * 32 + ((lane >> 4) << 3) + (lane & 7);
    const int bkof = ((lane >> 3) & 1) << 3;

#pragma unroll 1
    for (int ks = 0; ks < 8; ++ks) {
        int k0 = ks * 16;
        uint32_t ah[2][4], al[2][4], bh[2][4], bl[2][4];
#pragma unroll
        for (int mt = 0; mt < 2; ++mt) {
            uint32_t off = (uint32_t)((arow + mt * 16) * SROW + k0 + akof) * 2;
            ldsm4(ah[mt][0], ah[mt][1], ah[mt][2], ah[mt][3], sbase + A_H * 2 + off);
            ldsm4(al[mt][0], al[mt][1], al[mt][2], al[mt][3], sbase + A_L * 2 + off);
        }
#pragma unroll
        for (int np = 0; np < 2; ++np) {
            uint32_t off = (uint32_t)((bnrow + np * 16) * SROW + k0 + bkof) * 2;
            ldsm4(bh[np][0], bh[np][1], bh[np][2], bh[np][3], sbase + B_H * 2 + off);
            ldsm4(bl[np][0], bl[np][1], bl[np][2], bl[np][3], sbase + B_L * 2 + off);
        }
#pragma unroll
        for (int mt = 0; mt < 2; ++mt)
#pragma unroll
            for (int nt = 0; nt < 4; ++nt) {
                const uint32_t* bhp = &bh[nt >> 1][(nt & 1) * 2];
                const uint32_t* blp = &bl[nt >> 1][(nt & 1) * 2];
                mma_bf16(acc[mt][nt], ah[mt], bhp);
                mma_bf16(acc[mt][nt], ah[mt], blp);
                mma_bf16(acc[mt][nt], al[mt], bhp);
            }
    }

    // ---- epilogue ----
    const int grp = lane >> 2, qp = lane & 3;
    float2 bv[4];
#pragma unroll
    for (int nt = 0; nt < 4; ++nt) {
        int col = bn * 128 + wn * 32 + nt * 8 + qp * 2;
        bv[nt] = *(const float2*)(bias + col);
    }
#pragma unroll
    for (int mt = 0; mt < 2; ++mt) {
        int row = bm * 64 + wm * 32 + mt * 16 + grp;
#pragma unroll
        for (int nt = 0; nt < 4; ++nt) {
            int col = bn * 128 + wn * 32 + nt * 8 + qp * 2;
            float2 v0 = {acc[mt][nt][0] + bv[nt].x, acc[mt][nt][1] + bv[nt].y};
            float2 v1 = {acc[mt][nt][2] + bv[nt].x, acc[mt][nt][3] + bv[nt].y};
            *(float2*)(C + (size_t)row * Nc + col) = v0;
            *(float2*)(C + (size_t)(row + 8) * Nc + col) = v1;
        }
    }
}

// ---------------- fused edge message + deterministic aggregation ----------------
__global__ __launch_bounds__(128) void k_edge(const float* __restrict__ Wmsg,
                                              const float* __restrict__ bmsg) {
    int lane = threadIdx.x & 31;
    int nl = threadIdx.x >> 5;
    int n = blockIdx.x * 4 + nl;
    int b = blockIdx.y;
    float4 we = *(const float4*)(Wmsg + 256 * 128 + lane * 4);
    float4 bm = *(const float4*)(bmsg + lane * 4);
    const float* bigb = g_big + (size_t)b * NN * 640;
    float4 ht = *(const float4*)(bigb + (size_t)n * 640 + 128 + lane * 4);
    float4 base = {ht.x + bm.x, ht.y + bm.y, ht.z + bm.z, ht.w + bm.w};
    const float* efb = g_ef + (size_t)b * EE;
    int s0 = g_off[n], s1 = g_off[n + 1];
    float4 acc = {0.f, 0.f, 0.f, 0.f};
    int s = s0;
    for (; s + 2 <= s1; s += 2) {
        int sr0 = g_esrc[s], sr1 = g_esrc[s + 1];
        float e0 = efb[s], e1 = efb[s + 1];
        float4 h0 = *(const float4*)(bigb + (size_t)sr0 * 640 + lane * 4);
        float4 h1 = *(const float4*)(bigb + (size_t)sr1 * 640 + lane * 4);
        acc.x += selu_f(h0.x + base.x + e0 * we.x) + selu_f(h1.x + base.x + e1 * we.x);
        acc.y += selu_f(h0.y + base.y + e0 * we.y) + selu_f(h1.y + base.y + e1 * we.y);
        acc.z += selu_f(h0.z + base.z + e0 * we.z) + selu_f(h1.z + base.z + e1 * we.z);
        acc.w += selu_f(h0.w + base.w + e0 * we.w) + selu_f(h1.w + base.w + e1 * we.w);
    }
    if (s < s1) {
        int sr0 = g_esrc[s];
        float e0 = efb[s];
        float4 h0 = *(const float4*)(bigb + (size_t)sr0 * 640 + lane * 4);
        acc.x += selu_f(h0.x + base.x + e0 * we.x);
        acc.y += selu_f(h0.y + base.y + e0 * we.y);
        acc.z += selu_f(h0.z + base.z + e0 * we.z);
        acc.w += selu_f(h0.w + base.w + e0 * we.w);
    }
    *(float4*)(g_agg + ((size_t)(b * NN + n)) * DD + lane * 4) = acc;
}

// ---------------- GRU elementwise ----------------
__global__ void k_gru(const float* __restrict__ hprev) {
    int t = blockIdx.x * blockDim.x + threadIdx.x;
    if (t >= BB * NN * DD) return;
    int row = t >> 7, d = t & 127;
    const float* gi = g_gi + (size_t)row * 384;
    const float* gh = g_big + (size_t)row * 640 + 256;
    float ir = gi[d], iz = gi[128 + d], in_ = gi[256 + d];
    float hr = gh[d], hz = gh[128 + d], hn = gh[256 + d];
    float h = hprev[t];
    float r = 1.f / (1.f + __expf(-(ir + hr)));
    float z = 1.f / (1.f + __expf(-(iz + hz)));
    float nv = tanhf(in_ + r * hn);
    g_h[t] = (1.f - z) * nv + z * h;
}

// ---------------- pooling + readout head ----------------
__global__ void k_pool() {
    int c = blockIdx.x, b = blockIdx.y, d = threadIdx.x;
    const float* hb = g_h + ((size_t)b * NN + c * 64) * DD + d;
    float s = 0.f;
#pragma unroll 8
    for (int n = 0; n < 64; ++n) s += hb[(size_t)n * DD];
    g_part[(b * 16 + c) * DD + d] = s;
}

__global__ void k_head(const float* __restrict__ Wr1, const float* __restrict__ br1,
                       const float* __restrict__ Wr2, const float* __restrict__ br2,
                       const float* __restrict__ Wpol, const float* __restrict__ bpol,
                       float* __restrict__ out) {
    int b = blockIdx.x, d = threadIdx.x;
    __shared__ float p[128], q[128];
    float s = 0.f;
#pragma unroll
    for (int c = 0; c < 16; ++c) s += g_part[(b * 16 + c) * DD + d];
    p[d] = s;
    __syncthreads();
    float y = br1[d];
#pragma unroll 8
    for (int k = 0; k < 128; ++k) y = fmaf(p[k], Wr1[k * 128 + d], y);
    q[d] = selu_f(y);
    __syncthreads();
    y = br2[d];
#pragma unroll 8
    for (int k = 0; k < 128; ++k) y = fmaf(q[k], Wr2[k * 128 + d], y);
    float p2 = selu_f(y);
    __syncthreads();
    p[d] = p2;
    __syncthreads();
    if (d < 64) {
        float o = bpol[d];
#pragma unroll 8
        for (int k = 0; k < 128; ++k) o = fmaf(p[k], Wpol[k * 64 + d], o);
        out[b * 64 + d] = o;
    }
}

// ---------------- launch ----------------
extern "C" void kernel_launch(void* const* d_in, const int* in_sizes, int n_in,
                              void* d_out, int out_size) {
    const float* nf   = (const float*)d_in[0];
    const float* edge = (const float*)d_in[1];
    const int*   src  = (const int*)d_in[2];
    const int*   tgt  = (const int*)d_in[3];
    const float* Wmsg = (const float*)d_in[4];
    const float* bmsg = (const float*)d_in[5];
    const float* Wih  = (const float*)d_in[6];
    const float* Whh  = (const float*)d_in[7];
    const float* bih  = (const float*)d_in[8];
    const float* bhh  = (const float*)d_in[9];
    const float* Wr1  = (const float*)d_in[10];
    const float* br1  = (const float*)d_in[11];
    const float* Wr2  = (const float*)d_in[12];
    const float* br2  = (const float*)d_in[13];
    const float* Wpol = (const float*)d_in[14];
    const float* bpol = (const float*)d_in[15];
    float* out = (float*)d_out;

    float *g_h_p, *g_big_p, *g_gi_p, *g_bias1_p, *agg_p;
    __nv_bfloat16 *wbh_p, *wbl_p, *wih_h_p, *wih_l_p;
    cudaGetSymbolAddress((void**)&g_h_p, g_h);
    cudaGetSymbolAddress((void**)&g_big_p, g_big);
    cudaGetSymbolAddress((void**)&g_gi_p, g_gi);
    cudaGetSymbolAddress((void**)&g_bias1_p, g_bias1);
    cudaGetSymbolAddress((void**)&wbh_p, g_Wbh);
    cudaGetSymbolAddress((void**)&wbl_p, g_Wbl);
    cudaGetSymbolAddress((void**)&wih_h_p, g_Wih_h);
    cudaGetSymbolAddress((void**)&wih_l_p, g_Wih_l);
    cudaGetSymbolAddress((void**)&agg_p, g_agg);

    cudaFuncSetAttribute(k_mm<640>, cudaFuncAttributeMaxDynamicSharedMemorySize, MM_SMEM);
    cudaFuncSetAttribute(k_mm<384>, cudaFuncAttributeMaxDynamicSharedMemorySize, MM_SMEM);

    // launch index 3 == first k_mm<640> (profiled)
    k_pack<<<320, 256>>>(Wmsg, Whh, bhh, Wih);
    k_cnt<<<CH, 256>>>(tgt);
    k_tot<<<8, 128>>>();
    k_mm<640><<<dim3(5, 256), 256, MM_SMEM>>>(nf, wbh_p, wbl_p, g_bias1_p, g_big_p);
    k_scanx<<<1, NN>>>();
    k_offk<<<8, 128>>>();
    k_fill<<<CH, 32>>>(tgt, src);
    k_ef<<<(BB * EE + 255) / 256, 256>>>(edge, src, tgt);

    for (int it = 0; it < DIAM; ++it) {
        if (it > 0)
            k_mm<640><<<dim3(5, 256), 256, MM_SMEM>>>(g_h_p, wbh_p, wbl_p, g_bias1_p, g_big_p);
        k_edge<<<dim3(NN / 4, BB), 128>>>(Wmsg, bmsg);
        k_mm<384><<<dim3(3, 256), 256, MM_SMEM>>>(agg_p, wih_h_p, wih_l_p, bih, g_gi_p);
        k_gru<<<(BB * NN * DD + 255) / 256, 256>>>(it == 0 ? nf : g_h_p);
    }

    k_pool<<<dim3(16, BB), 128>>>();
    k_head<<<BB, 128>>>(Wr1, br1, Wr2, br2, Wpol, bpol, out);
}

// round 7
// speedup vs baseline: 2.3680x; 1.0925x over previous
#include <cuda_runtime.h>
#include <cuda_bf16.h>
#include <cstdint>

// Problem constants
#define BB   16
#define NN   1024
#define DD   128
#define EE   16384
#define AA   64
#define DIAM 3
#define CH   64           // edge chunks for CSR build
#define CE   (EE / CH)    // 256 edges per chunk

// ---------------- device scratch (no allocations allowed) ----------------
__device__ float g_h[BB * NN * DD];             // node state fp32
__device__ __nv_bfloat16 g_hh[BB * NN * DD];    // h hi
__device__ __nv_bfloat16 g_hl[BB * NN * DD];    // h lo
__device__ float g_big[BB * NN * 640];          // [hs|ht|gh] per node
__device__ __nv_bfloat16 g_aggh[BB * NN * DD];  // agg hi
__device__ __nv_bfloat16 g_aggl[BB * NN * DD];  // agg lo
__device__ float g_gi[BB * NN * 384];           // gi = agg@Wih^T
__device__ float g_ef[BB * EE];                 // edge scalars, CSR slot order
__device__ __nv_bfloat16 g_Wbh[640 * 128];      // packed big weight, hi, [n][k]
__device__ __nv_bfloat16 g_Wbl[640 * 128];      // lo
__device__ __nv_bfloat16 g_Wih_h[384 * 128];    // W_ih hi, [n][k]
__device__ __nv_bfloat16 g_Wih_l[384 * 128];    // lo
__device__ float g_bias1[640];                  // [0,0,b_hh]
__device__ int   g_ccnt[CH * NN];
__device__ int   g_deg[NN];
__device__ int   g_off[NN + 1];
__device__ int   g_eid[EE];
__device__ int   g_esrc[EE];
__device__ float g_part[BB * 16 * DD];

__device__ __forceinline__ float selu_f(float x) {
    const float sc = 1.0507009873554805f, al = 1.6732632423543772f;
    return x > 0.f ? sc * x : sc * al * (__expf(x) - 1.f);
}

// ---------------- setup kernels ----------------
__global__ void k_pack(const float* __restrict__ Wmsg, const float* __restrict__ Whh,
                       const float* __restrict__ bhh, const float* __restrict__ Wih) {
    int t = blockIdx.x * blockDim.x + threadIdx.x;
    if (t < 640 * 128) {
        int n = t >> 7, k = t & 127;
        float v;
        if (n < 128)       v = Wmsg[k * 128 + n];                 // src part
        else if (n < 256)  v = Wmsg[(128 + k) * 128 + (n - 128)]; // tgt part
        else               v = Whh[(n - 256) * 128 + k];          // W_hh^T
        __nv_bfloat16 hi = __float2bfloat16(v);
        g_Wbh[t] = hi;
        g_Wbl[t] = __float2bfloat16(v - __bfloat162float(hi));
    }
    if (t < 384 * 128) {
        float v = Wih[t];  // Wih is [384][128] row-major == [n][k]
        __nv_bfloat16 hi = __float2bfloat16(v);
        g_Wih_h[t] = hi;
        g_Wih_l[t] = __float2bfloat16(v - __bfloat162float(hi));
    }
    if (t < 640) g_bias1[t] = (t < 256) ? 0.f : bhh[t - 256];
}

// initial h (= node_features) -> bf16 hi/lo
__global__ void k_hcvt(const float* __restrict__ nf) {
    int t = blockIdx.x * blockDim.x + threadIdx.x;
    if (t < BB * NN * DD) {
        float v = nf[t];
        __nv_bfloat16 hi = __float2bfloat16(v);
        g_hh[t] = hi;
        g_hl[t] = __float2bfloat16(v - __bfloat162float(hi));
    }
}

// ---- CSR build: chunked histogram (deterministic stable order) ----
__global__ void k_cnt(const int* __restrict__ tgt) {  // grid CH, block 256
    __shared__ int c[NN];
    for (int i = threadIdx.x; i < NN; i += 256) c[i] = 0;
    __syncthreads();
    int e = blockIdx.x * CE + threadIdx.x;
    atomicAdd(&c[tgt[e]], 1);
    __syncthreads();
    for (int i = threadIdx.x; i < NN; i += 256) g_ccnt[blockIdx.x * NN + i] = c[i];
}

__global__ void k_tot() {  // grid 8, block 128
    int n = blockIdx.x * 128 + threadIdx.x;
    int s = 0;
#pragma unroll
    for (int c = 0; c < CH; ++c) s += g_ccnt[c * NN + n];
    g_deg[n] = s;
}

__global__ void k_scanx() {  // 1 block, 1024 threads
    __shared__ int s[NN];
    int n = threadIdx.x;
    s[n] = g_deg[n];
    __syncthreads();
    for (int o = 1; o < NN; o <<= 1) {
        int x = (n >= o) ? s[n - o] : 0;
        __syncthreads();
        s[n] += x;
        __syncthreads();
    }
    g_off[n + 1] = s[n];
    if (n == 0) g_off[0] = 0;
}

__global__ void k_offk() {  // grid 8, block 128
    int n = blockIdx.x * 128 + threadIdx.x;
    int run = g_off[n];
#pragma unroll
    for (int c = 0; c < CH; ++c) {
        int v = g_ccnt[c * NN + n];
        g_ccnt[c * NN + n] = run;
        run += v;
    }
}

__global__ void k_fill(const int* __restrict__ tgt, const int* __restrict__ src) {
    __shared__ int ctr[NN];
    int lane = threadIdx.x;
    int chunk = blockIdx.x;
    for (int i = lane; i < NN; i += 32) ctr[i] = g_ccnt[chunk * NN + i];
    __syncwarp();
    for (int r = 0; r < CE / 32; ++r) {
        int e = chunk * CE + r * 32 + lane;
        int t = tgt[e];
        unsigned mask = __match_any_sync(0xffffffffu, t);
        int leader = __ffs(mask) - 1;
        int rank = __popc(mask & ((1u << lane) - 1u));
        int base = 0;
        if (lane == leader) { base = ctr[t]; ctr[t] = base + __popc(mask); }
        base = __shfl_sync(0xffffffffu, base, leader);
        g_eid[base + rank] = e;
        g_esrc[base + rank] = src[e];
        __syncwarp();
    }
}

__global__ void k_ef(const float* __restrict__ edge, const int* __restrict__ src,
                     const int* __restrict__ tgt) {
    int t = blockIdx.x * blockDim.x + threadIdx.x;
    if (t < BB * EE) {
        int b = t / EE, slot = t % EE;
        int e = g_eid[slot];
        g_ef[t] = edge[(size_t)b * NN * NN + (size_t)src[e] * NN + tgt[e]];
    }
}

// ---------------- split-bf16 HMMA GEMM, cp.async + reg-pipelined ----------------
// C[16384, Nc] = A[16384,128] @ W[128,Nc] + bias  via  Ah·Bh + Ah·Bl + Al·Bh
// Block: 64 rows x 128 cols, whole K in smem. 8 warps: 2(m) x 4(n), warp tile 32x32.
#define SROW 136                     // padded row in bf16 elems (conflict-free ldmatrix)
#define A_H 0
#define A_L (64 * SROW)
#define B_H (2 * 64 * SROW)
#define B_L (2 * 64 * SROW + 128 * SROW)
#define MM_SMEM ((2 * 64 + 2 * 128) * SROW * 2)   // 104448 bytes -> 2 blocks/SM

__device__ __forceinline__ void cp16(uint32_t dst, const void* src) {
    asm volatile("cp.async.cg.shared.global [%0], [%1], 16;" :: "r"(dst), "l"(src));
}
__device__ __forceinline__ void ldsm4(uint32_t& r0, uint32_t& r1, uint32_t& r2, uint32_t& r3,
                                      uint32_t addr) {
    asm volatile("ldmatrix.sync.aligned.m8n8.x4.shared.b16 {%0,%1,%2,%3},[%4];"
                 : "=r"(r0), "=r"(r1), "=r"(r2), "=r"(r3) : "r"(addr));
}
__device__ __forceinline__ void mma_bf16(float* d, const uint32_t* a, const uint32_t* b) {
    asm volatile(
        "mma.sync.aligned.m16n8k16.row.col.f32.bf16.bf16.f32 "
        "{%0,%1,%2,%3},{%4,%5,%6,%7},{%8,%9},{%0,%1,%2,%3};"
        : "+f"(d[0]), "+f"(d[1]), "+f"(d[2]), "+f"(d[3])
        : "r"(a[0]), "r"(a[1]), "r"(a[2]), "r"(a[3]), "r"(b[0]), "r"(b[1]));
}

template <int Nc>
__global__ __launch_bounds__(256, 2) void k_mm(const __nv_bfloat16* __restrict__ Ahg,
                                               const __nv_bfloat16* __restrict__ Alg,
                                               const __nv_bfloat16* __restrict__ Bhg,
                                               const __nv_bfloat16* __restrict__ Blg,
                                               const float* __restrict__ bias,
                                               float* __restrict__ C) {
    extern __shared__ char smraw[];
    const int tid = threadIdx.x;
    const int bn = blockIdx.x, bm = blockIdx.y;
    const int lane = tid & 31, w = tid >> 5;
    const int wm = w >> 2, wn = w & 3;       // warp grid 2 x 4

    uint32_t sbase = (uint32_t)__cvta_generic_to_shared(smraw);

    // ---- async loads: pure 16B copies (operands pre-converted by producers) ----
    const __nv_bfloat16* Aho = Ahg + (size_t)(bm * 64) * 128;
    const __nv_bfloat16* Alo = Alg + (size_t)(bm * 64) * 128;
#pragma unroll
    for (int i = 0; i < 4; ++i) {            // A: 1024 chunks hi+lo
        int idx = tid + i * 256;
        int row = idx >> 4, c8 = (idx & 15) * 8;
        uint32_t so = (uint32_t)(row * SROW + c8) * 2;
        size_t g = (size_t)row * 128 + c8;
        cp16(sbase + A_H * 2 + so, Aho + g);
        cp16(sbase + A_L * 2 + so, Alo + g);
    }
    const __nv_bfloat16* Bho = Bhg + (size_t)(bn * 128) * 128;
    const __nv_bfloat16* Blo = Blg + (size_t)(bn * 128) * 128;
#pragma unroll
    for (int i = 0; i < 8; ++i) {            // B: 2048 chunks hi+lo
        int idx = tid + i * 256;
        int row = idx >> 4, c8 = (idx & 15) * 8;
        uint32_t so = (uint32_t)(row * SROW + c8) * 2;
        size_t g = (size_t)row * 128 + c8;
        cp16(sbase + B_H * 2 + so, Bho + g);
        cp16(sbase + B_L * 2 + so, Blo + g);
    }
    asm volatile("cp.async.commit_group;" ::: "memory");
    asm volatile("cp.async.wait_group 0;" ::: "memory");
    __syncthreads();

    float acc[2][4][4];
#pragma unroll
    for (int mt = 0; mt < 2; ++mt)
#pragma unroll
        for (int nt = 0; nt < 4; ++nt)
#pragma unroll
            for (int q = 0; q < 4; ++q) acc[mt][nt][q] = 0.f;

    const int arow = wm * 32 + (lane & 15);
    const int akof = (lane >> 4) << 3;
    const int bnrow = wn * 32 + ((lane >> 4) << 3) + (lane & 7);
    const int bkof = ((lane >> 3) & 1) << 3;

    // fragment double buffer
    uint32_t ah[2][2][4], al[2][2][4], bh[2][2][4], bl[2][2][4];

    auto ldfr = [&](int ks, int buf) {
        int k0 = ks * 16;
#pragma unroll
        for (int mt = 0; mt < 2; ++mt) {
            uint32_t off = (uint32_t)((arow + mt * 16) * SROW + k0 + akof) * 2;
            ldsm4(ah[buf][mt][0], ah[buf][mt][1], ah[buf][mt][2], ah[buf][mt][3],
                  sbase + A_H * 2 + off);
            ldsm4(al[buf][mt][0], al[buf][mt][1], al[buf][mt][2], al[buf][mt][3],
                  sbase + A_L * 2 + off);
        }
#pragma unroll
        for (int np = 0; np < 2; ++np) {
            uint32_t off = (uint32_t)((bnrow + np * 16) * SROW + k0 + bkof) * 2;
            ldsm4(bh[buf][np][0], bh[buf][np][1], bh[buf][np][2], bh[buf][np][3],
                  sbase + B_H * 2 + off);
            ldsm4(bl[buf][np][0], bl[buf][np][1], bl[buf][np][2], bl[buf][np][3],
                  sbase + B_L * 2 + off);
        }
    };

    ldfr(0, 0);
#pragma unroll
    for (int ks = 0; ks < 8; ++ks) {
        int buf = ks & 1;
        if (ks < 7) ldfr(ks + 1, buf ^ 1);
#pragma unroll
        for (int mt = 0; mt < 2; ++mt)
#pragma unroll
            for (int nt = 0; nt < 4; ++nt) {
                const uint32_t* bhp = &bh[buf][nt >> 1][(nt & 1) * 2];
                const uint32_t* blp = &bl[buf][nt >> 1][(nt & 1) * 2];
                mma_bf16(acc[mt][nt], ah[buf][mt], bhp);
                mma_bf16(acc[mt][nt], ah[buf][mt], blp);
                mma_bf16(acc[mt][nt], al[buf][mt], bhp);
            }
    }

    // ---- epilogue ----
    const int grp = lane >> 2, qp = lane & 3;
    float2 bv[4];
#pragma unroll
    for (int nt = 0; nt < 4; ++nt) {
        int col = bn * 128 + wn * 32 + nt * 8 + qp * 2;
        bv[nt] = *(const float2*)(bias + col);
    }
#pragma unroll
    for (int mt = 0; mt < 2; ++mt) {
        int row = bm * 64 + wm * 32 + mt * 16 + grp;
#pragma unroll
        for (int nt = 0; nt < 4; ++nt) {
            int col = bn * 128 + wn * 32 + nt * 8 + qp * 2;
            float2 v0 = {acc[mt][nt][0] + bv[nt].x, acc[mt][nt][1] + bv[nt].y};
            float2 v1 = {acc[mt][nt][2] + bv[nt].x, acc[mt][nt][3] + bv[nt].y};
            *(float2*)(C + (size_t)row * Nc + col) = v0;
            *(float2*)(C + (size_t)(row + 8) * Nc + col) = v1;
        }
    }
}

// ---------------- fused edge message + deterministic aggregation ----------------
__global__ __launch_bounds__(128) void k_edge(const float* __restrict__ Wmsg,
                                              const float* __restrict__ bmsg) {
    int lane = threadIdx.x & 31;
    int nl = threadIdx.x >> 5;
    int n = blockIdx.x * 4 + nl;
    int b = blockIdx.y;
    float4 we = *(const float4*)(Wmsg + 256 * 128 + lane * 4);
    float4 bm = *(const float4*)(bmsg + lane * 4);
    const float* bigb = g_big + (size_t)b * NN * 640;
    float4 ht = *(const float4*)(bigb + (size_t)n * 640 + 128 + lane * 4);
    float4 base = {ht.x + bm.x, ht.y + bm.y, ht.z + bm.z, ht.w + bm.w};
    const float* efb = g_ef + (size_t)b * EE;
    int s0 = g_off[n], s1 = g_off[n + 1];
    float4 acc = {0.f, 0.f, 0.f, 0.f};
    int s = s0;
    for (; s + 2 <= s1; s += 2) {
        int sr0 = g_esrc[s], sr1 = g_esrc[s + 1];
        float e0 = efb[s], e1 = efb[s + 1];
        float4 h0 = *(const float4*)(bigb + (size_t)sr0 * 640 + lane * 4);
        float4 h1 = *(const float4*)(bigb + (size_t)sr1 * 640 + lane * 4);
        acc.x += selu_f(h0.x + base.x + e0 * we.x) + selu_f(h1.x + base.x + e1 * we.x);
        acc.y += selu_f(h0.y + base.y + e0 * we.y) + selu_f(h1.y + base.y + e1 * we.y);
        acc.z += selu_f(h0.z + base.z + e0 * we.z) + selu_f(h1.z + base.z + e1 * we.z);
        acc.w += selu_f(h0.w + base.w + e0 * we.w) + selu_f(h1.w + base.w + e1 * we.w);
    }
    if (s < s1) {
        int sr0 = g_esrc[s];
        float e0 = efb[s];
        float4 h0 = *(const float4*)(bigb + (size_t)sr0 * 640 + lane * 4);
        acc.x += selu_f(h0.x + base.x + e0 * we.x);
        acc.y += selu_f(h0.y + base.y + e0 * we.y);
        acc.z += selu_f(h0.z + base.z + e0 * we.z);
        acc.w += selu_f(h0.w + base.w + e0 * we.w);
    }
    // write bf16 hi/lo (consumed by k_mm<384>)
    size_t o = ((size_t)(b * NN + n)) * DD + lane * 4;
    float a4[4] = {acc.x, acc.y, acc.z, acc.w};
    __nv_bfloat16 hi4[4], lo4[4];
#pragma unroll
    for (int j = 0; j < 4; ++j) {
        hi4[j] = __float2bfloat16(a4[j]);
        lo4[j] = __float2bfloat16(a4[j] - __bfloat162float(hi4[j]));
    }
    *(uint2*)(g_aggh + o) = *(uint2*)hi4;
    *(uint2*)(g_aggl + o) = *(uint2*)lo4;
}

// ---------------- GRU elementwise ----------------
__global__ void k_gru(const float* __restrict__ hprev) {
    int t = blockIdx.x * blockDim.x + threadIdx.x;
    if (t >= BB * NN * DD) return;
    int row = t >> 7, d = t & 127;
    const float* gi = g_gi + (size_t)row * 384;
    const float* gh = g_big + (size_t)row * 640 + 256;
    float ir = gi[d], iz = gi[128 + d], in_ = gi[256 + d];
    float hr = gh[d], hz = gh[128 + d], hn = gh[256 + d];
    float h = hprev[t];
    float r = 1.f / (1.f + __expf(-(ir + hr)));
    float z = 1.f / (1.f + __expf(-(iz + hz)));
    float nv = tanhf(in_ + r * hn);
    float hn2 = (1.f - z) * nv + z * h;
    g_h[t] = hn2;
    __nv_bfloat16 hi = __float2bfloat16(hn2);
    g_hh[t] = hi;
    g_hl[t] = __float2bfloat16(hn2 - __bfloat162float(hi));
}

// ---------------- pooling + readout head ----------------
__global__ void k_pool() {
    int c = blockIdx.x, b = blockIdx.y, d = threadIdx.x;
    const float* hb = g_h + ((size_t)b * NN + c * 64) * DD + d;
    float s = 0.f;
#pragma unroll 8
    for (int n = 0; n < 64; ++n) s += hb[(size_t)n * DD];
    g_part[(b * 16 + c) * DD + d] = s;
}

__global__ void k_head(const float* __restrict__ Wr1, const float* __restrict__ br1,
                       const float* __restrict__ Wr2, const float* __restrict__ br2,
                       const float* __restrict__ Wpol, const float* __restrict__ bpol,
                       float* __restrict__ out) {
    int b = blockIdx.x, d = threadIdx.x;
    __shared__ float p[128], q[128];
    float s = 0.f;
#pragma unroll
    for (int c = 0; c < 16; ++c) s += g_part[(b * 16 + c) * DD + d];
    p[d] = s;
    __syncthreads();
    float y = br1[d];
#pragma unroll 8
    for (int k = 0; k < 128; ++k) y = fmaf(p[k], Wr1[k * 128 + d], y);
    q[d] = selu_f(y);
    __syncthreads();
    y = br2[d];
#pragma unroll 8
    for (int k = 0; k < 128; ++k) y = fmaf(q[k], Wr2[k * 128 + d], y);
    float p2 = selu_f(y);
    __syncthreads();
    p[d] = p2;
    __syncthreads();
    if (d < 64) {
        float o = bpol[d];
#pragma unroll 8
        for (int k = 0; k < 128; ++k) o = fmaf(p[k], Wpol[k * 64 + d], o);
        out[b * 64 + d] = o;
    }
}

// ---------------- launch ----------------
extern "C" void kernel_launch(void* const* d_in, const int* in_sizes, int n_in,
                              void* d_out, int out_size) {
    const float* nf   = (const float*)d_in[0];
    const float* edge = (const float*)d_in[1];
    const int*   src  = (const int*)d_in[2];
    const int*   tgt  = (const int*)d_in[3];
    const float* Wmsg = (const float*)d_in[4];
    const float* bmsg = (const float*)d_in[5];
    const float* Wih  = (const float*)d_in[6];
    const float* Whh  = (const float*)d_in[7];
    const float* bih  = (const float*)d_in[8];
    const float* bhh  = (const float*)d_in[9];
    const float* Wr1  = (const float*)d_in[10];
    const float* br1  = (const float*)d_in[11];
    const float* Wr2  = (const float*)d_in[12];
    const float* br2  = (const float*)d_in[13];
    const float* Wpol = (const float*)d_in[14];
    const float* bpol = (const float*)d_in[15];
    float* out = (float*)d_out;

    float *g_h_p, *g_big_p, *g_gi_p, *g_bias1_p;
    __nv_bfloat16 *wbh_p, *wbl_p, *wih_h_p, *wih_l_p, *hh_p, *hl_p, *aggh_p, *aggl_p;
    cudaGetSymbolAddress((void**)&g_h_p, g_h);
    cudaGetSymbolAddress((void**)&g_big_p, g_big);
    cudaGetSymbolAddress((void**)&g_gi_p, g_gi);
    cudaGetSymbolAddress((void**)&g_bias1_p, g_bias1);
    cudaGetSymbolAddress((void**)&wbh_p, g_Wbh);
    cudaGetSymbolAddress((void**)&wbl_p, g_Wbl);
    cudaGetSymbolAddress((void**)&wih_h_p, g_Wih_h);
    cudaGetSymbolAddress((void**)&wih_l_p, g_Wih_l);
    cudaGetSymbolAddress((void**)&hh_p, g_hh);
    cudaGetSymbolAddress((void**)&hl_p, g_hl);
    cudaGetSymbolAddress((void**)&aggh_p, g_aggh);
    cudaGetSymbolAddress((void**)&aggl_p, g_aggl);

    cudaFuncSetAttribute(k_mm<640>, cudaFuncAttributeMaxDynamicSharedMemorySize, MM_SMEM);
    cudaFuncSetAttribute(k_mm<384>, cudaFuncAttributeMaxDynamicSharedMemorySize, MM_SMEM);

    // launch index 3 == first k_mm<640> (profiled)
    k_pack<<<320, 256>>>(Wmsg, Whh, bhh, Wih);
    k_cnt<<<CH, 256>>>(tgt);
    k_hcvt<<<(BB * NN * DD + 255) / 256, 256>>>(nf);
    k_mm<640><<<dim3(5, 256), 256, MM_SMEM>>>(hh_p, hl_p, wbh_p, wbl_p, g_bias1_p, g_big_p);
    k_tot<<<8, 128>>>();
    k_scanx<<<1, NN>>>();
    k_offk<<<8, 128>>>();
    k_fill<<<CH, 32>>>(tgt, src);
    k_ef<<<(BB * EE + 255) / 256, 256>>>(edge, src, tgt);

    for (int it = 0; it < DIAM; ++it) {
        if (it > 0)
            k_mm<640><<<dim3(5, 256), 256, MM_SMEM>>>(hh_p, hl_p, wbh_p, wbl_p,
                                                      g_bias1_p, g_big_p);
        k_edge<<<dim3(NN / 4, BB), 128>>>(Wmsg, bmsg);
        k_mm<384><<<dim3(3, 256), 256, MM_SMEM>>>(aggh_p, aggl_p, wih_h_p, wih_l_p,
                                                  bih, g_gi_p);
        k_gru<<<(BB * NN * DD + 255) / 256, 256>>>(it == 0 ? nf : g_h_p);
    }

    k_pool<<<dim3(16, BB), 128>>>();
    k_head<<<BB, 128>>>(Wr1, br1, Wr2, br2, Wpol, bpol, out);
}

// round 8
// speedup vs baseline: 2.4483x; 1.0339x over previous
#include <cuda_runtime.h>
#include <cuda_bf16.h>
#include <cstdint>

// Problem constants
#define BB   16
#define NN   1024
#define DD   128
#define EE   16384
#define AA   64
#define DIAM 3
#define CH   64           // edge chunks for CSR build
#define CE   (EE / CH)    // 256 edges per chunk

// ---------------- device scratch (no allocations allowed) ----------------
__device__ float g_h[BB * NN * DD];             // node state fp32
__device__ __nv_bfloat16 g_hh[BB * NN * DD];    // h hi
__device__ __nv_bfloat16 g_hl[BB * NN * DD];    // h lo
__device__ float g_big[BB * NN * 640];          // [hs|ht|gh] per node
__device__ __nv_bfloat16 g_aggh[BB * NN * DD];  // agg hi
__device__ __nv_bfloat16 g_aggl[BB * NN * DD];  // agg lo
__device__ float g_gi[BB * NN * 384];           // gi = agg@Wih^T
__device__ float g_ef[BB * EE];                 // edge scalars, CSR slot order
__device__ __nv_bfloat16 g_Wbh[640 * 128];      // packed big weight, hi, [n][k]
__device__ __nv_bfloat16 g_Wbl[640 * 128];      // lo
__device__ __nv_bfloat16 g_Wih_h[384 * 128];    // W_ih hi, [n][k]
__device__ __nv_bfloat16 g_Wih_l[384 * 128];    // lo
__device__ float g_bias1[640];                  // [0,0,b_hh]
__device__ int   g_ccnt[CH * NN];
__device__ int   g_deg[NN];
__device__ int   g_off[NN + 1];
__device__ int   g_eid[EE];
__device__ int   g_esrc[EE];
__device__ float g_part[BB * 16 * DD];

__device__ __forceinline__ float selu_f(float x) {
    const float sc = 1.0507009873554805f, al = 1.6732632423543772f;
    return x > 0.f ? sc * x : sc * al * (__expf(x) - 1.f);
}

// ---------------- setup kernels ----------------
__global__ void k_pack(const float* __restrict__ Wmsg, const float* __restrict__ Whh,
                       const float* __restrict__ bhh, const float* __restrict__ Wih) {
    int t = blockIdx.x * blockDim.x + threadIdx.x;
    if (t < 640 * 128) {
        int n = t >> 7, k = t & 127;
        float v;
        if (n < 128)       v = Wmsg[k * 128 + n];                 // src part
        else if (n < 256)  v = Wmsg[(128 + k) * 128 + (n - 128)]; // tgt part
        else               v = Whh[(n - 256) * 128 + k];          // W_hh^T
        __nv_bfloat16 hi = __float2bfloat16(v);
        g_Wbh[t] = hi;
        g_Wbl[t] = __float2bfloat16(v - __bfloat162float(hi));
    }
    if (t < 384 * 128) {
        float v = Wih[t];  // Wih is [384][128] row-major == [n][k]
        __nv_bfloat16 hi = __float2bfloat16(v);
        g_Wih_h[t] = hi;
        g_Wih_l[t] = __float2bfloat16(v - __bfloat162float(hi));
    }
    if (t < 640) g_bias1[t] = (t < 256) ? 0.f : bhh[t - 256];
}

// initial h (= node_features) -> bf16 hi/lo
__global__ void k_hcvt(const float* __restrict__ nf) {
    int t = blockIdx.x * blockDim.x + threadIdx.x;
    if (t < BB * NN * DD) {
        float v = nf[t];
        __nv_bfloat16 hi = __float2bfloat16(v);
        g_hh[t] = hi;
        g_hl[t] = __float2bfloat16(v - __bfloat162float(hi));
    }
}

// ---- CSR build: chunked histogram (deterministic stable order) ----
__global__ void k_cnt(const int* __restrict__ tgt) {  // grid CH, block 256
    __shared__ int c[NN];
    for (int i = threadIdx.x; i < NN; i += 256) c[i] = 0;
    __syncthreads();
    int e = blockIdx.x * CE + threadIdx.x;
    atomicAdd(&c[tgt[e]], 1);
    __syncthreads();
    for (int i = threadIdx.x; i < NN; i += 256) g_ccnt[blockIdx.x * NN + i] = c[i];
}

__global__ void k_tot() {  // grid 8, block 128
    int n = blockIdx.x * 128 + threadIdx.x;
    int s = 0;
#pragma unroll
    for (int c = 0; c < CH; ++c) s += g_ccnt[c * NN + n];
    g_deg[n] = s;
}

__global__ void k_scanx() {  // 1 block, 1024 threads
    __shared__ int s[NN];
    int n = threadIdx.x;
    s[n] = g_deg[n];
    __syncthreads();
    for (int o = 1; o < NN; o <<= 1) {
        int x = (n >= o) ? s[n - o] : 0;
        __syncthreads();
        s[n] += x;
        __syncthreads();
    }
    g_off[n + 1] = s[n];
    if (n == 0) g_off[0] = 0;
}

__global__ void k_offk() {  // grid 8, block 128
    int n = blockIdx.x * 128 + threadIdx.x;
    int run = g_off[n];
#pragma unroll
    for (int c = 0; c < CH; ++c) {
        int v = g_ccnt[c * NN + n];
        g_ccnt[c * NN + n] = run;
        run += v;
    }
}

__global__ void k_fill(const int* __restrict__ tgt, const int* __restrict__ src) {
    __shared__ int ctr[NN];
    int lane = threadIdx.x;
    int chunk = blockIdx.x;
    for (int i = lane; i < NN; i += 32) ctr[i] = g_ccnt[chunk * NN + i];
    __syncwarp();
    for (int r = 0; r < CE / 32; ++r) {
        int e = chunk * CE + r * 32 + lane;
        int t = tgt[e];
        unsigned mask = __match_any_sync(0xffffffffu, t);
        int leader = __ffs(mask) - 1;
        int rank = __popc(mask & ((1u << lane) - 1u));
        int base = 0;
        if (lane == leader) { base = ctr[t]; ctr[t] = base + __popc(mask); }
        base = __shfl_sync(0xffffffffu, base, leader);
        g_eid[base + rank] = e;
        g_esrc[base + rank] = src[e];
        __syncwarp();
    }
}

__global__ void k_ef(const float* __restrict__ edge, const int* __restrict__ src,
                     const int* __restrict__ tgt) {
    int t = blockIdx.x * blockDim.x + threadIdx.x;
    if (t < BB * EE) {
        int b = t / EE, slot = t % EE;
        int e = g_eid[slot];
        g_ef[t] = edge[(size_t)b * NN * NN + (size_t)src[e] * NN + tgt[e]];
    }
}

// ---------------- persistent weight-stationary split-bf16 HMMA GEMM ----------------
// C[16384, Nc] = A[16384,128] @ W[128,Nc] + bias  via  Ah·Bh + Ah·Bl + Al·Bh
// One CTA: resident B panel (128 cols x 128 k), loops over 32-row A panels
// (double-buffered cp.async). 8 warps: 2(m) x 4(n), warp tile 16x32.
#define SROW 136                          // padded row in bf16 elems
#define B_H 0
#define B_L (128 * SROW)
#define A_BASE (256 * SROW)               // two buffers of (32 hi + 32 lo) rows
#define MM_SMEM (384 * SROW * 2)          // 104448 bytes -> 2 blocks/SM
#define MPAN 512                          // 16384 rows / 32

__device__ __forceinline__ void cp16(uint32_t dst, const void* src) {
    asm volatile("cp.async.cg.shared.global [%0], [%1], 16;" :: "r"(dst), "l"(src));
}
__device__ __forceinline__ void ldsm4(uint32_t& r0, uint32_t& r1, uint32_t& r2, uint32_t& r3,
                                      uint32_t addr) {
    asm volatile("ldmatrix.sync.aligned.m8n8.x4.shared.b16 {%0,%1,%2,%3},[%4];"
                 : "=r"(r0), "=r"(r1), "=r"(r2), "=r"(r3) : "r"(addr));
}
__device__ __forceinline__ void mma_bf16(float* d, const uint32_t* a, const uint32_t* b) {
    asm volatile(
        "mma.sync.aligned.m16n8k16.row.col.f32.bf16.bf16.f32 "
        "{%0,%1,%2,%3},{%4,%5,%6,%7},{%8,%9},{%0,%1,%2,%3};"
        : "+f"(d[0]), "+f"(d[1]), "+f"(d[2]), "+f"(d[3])
        : "r"(a[0]), "r"(a[1]), "r"(a[2]), "r"(a[3]), "r"(b[0]), "r"(b[1]));
}

template <int Nc>
__global__ __launch_bounds__(256, 2) void k_mm(const __nv_bfloat16* __restrict__ Ahg,
                                               const __nv_bfloat16* __restrict__ Alg,
                                               const __nv_bfloat16* __restrict__ Bhg,
                                               const __nv_bfloat16* __restrict__ Blg,
                                               const float* __restrict__ bias,
                                               float* __restrict__ C) {
    extern __shared__ char smraw[];
    const int tid = threadIdx.x;
    const int bn = blockIdx.x;
    const int step = gridDim.y;
    const int lane = tid & 31, w = tid >> 5;
    const int wm = w >> 2, wn = w & 3;       // warp grid 2(m) x 4(n)

    uint32_t sbase = (uint32_t)__cvta_generic_to_shared(smraw);

    // ---- load resident B panel (128 cols, hi+lo) ----
    const __nv_bfloat16* Bho = Bhg + (size_t)(bn * 128) * 128;
    const __nv_bfloat16* Blo = Blg + (size_t)(bn * 128) * 128;
#pragma unroll
    for (int i = 0; i < 8; ++i) {
        int idx = tid + i * 256;
        int row = idx >> 4, c8 = (idx & 15) * 8;
        uint32_t so = (uint32_t)(row * SROW + c8) * 2;
        size_t g = (size_t)row * 128 + c8;
        cp16(sbase + B_H * 2 + so, Bho + g);
        cp16(sbase + B_L * 2 + so, Blo + g);
    }

    auto loadA = [&](int bm, int buf) {
        const __nv_bfloat16* Aho = Ahg + (size_t)(bm * 32) * 128;
        const __nv_bfloat16* Alo = Alg + (size_t)(bm * 32) * 128;
        uint32_t ab = sbase + (uint32_t)(A_BASE + buf * 64 * SROW) * 2;
#pragma unroll
        for (int i = 0; i < 2; ++i) {
            int idx = tid + i * 256;
            int row = idx >> 4, c8 = (idx & 15) * 8;
            uint32_t so = (uint32_t)(row * SROW + c8) * 2;
            size_t g = (size_t)row * 128 + c8;
            cp16(ab + so, Aho + g);
            cp16(ab + (uint32_t)(32 * SROW) * 2 + so, Alo + g);
        }
    };

    const int bm0 = blockIdx.y;
    loadA(bm0, 0);
    asm volatile("cp.async.commit_group;" ::: "memory");   // group: B + A(panel0)

    // bias registers (per wn, qp)
    const int grp = lane >> 2, qp = lane & 3;
    float2 bv[4];
#pragma unroll
    for (int nt = 0; nt < 4; ++nt) {
        int col = bn * 128 + wn * 32 + nt * 8 + qp * 2;
        bv[nt] = *(const float2*)(bias + col);
    }

    const int arow = wm * 16 + (lane & 15);
    const int akof = (lane >> 4) << 3;
    const int bnrow = wn * 32 + ((lane >> 4) << 3) + (lane & 7);
    const int bkof = ((lane >> 3) & 1) << 3;

    int buf = 0;
    for (int bm = bm0; bm < MPAN; bm += step) {
        int nxt = bm + step;
        if (nxt < MPAN) {
            loadA(nxt, buf ^ 1);
            asm volatile("cp.async.commit_group;" ::: "memory");
            asm volatile("cp.async.wait_group 1;" ::: "memory");
        } else {
            asm volatile("cp.async.wait_group 0;" ::: "memory");
        }
        __syncthreads();

        uint32_t abase = sbase + (uint32_t)(A_BASE + buf * 64 * SROW) * 2;
        uint32_t lbase = abase + (uint32_t)(32 * SROW) * 2;

        float acc[4][4];
#pragma unroll
        for (int nt = 0; nt < 4; ++nt)
#pragma unroll
            for (int q = 0; q < 4; ++q) acc[nt][q] = 0.f;

        uint32_t ah[2][4], al[2][4], bh[2][2][4], bl[2][2][4];
        auto ldfr = [&](int ks, int fb) {
            int k0 = ks * 16;
            uint32_t aoff = (uint32_t)(arow * SROW + k0 + akof) * 2;
            ldsm4(ah[fb][0], ah[fb][1], ah[fb][2], ah[fb][3], abase + aoff);
            ldsm4(al[fb][0], al[fb][1], al[fb][2], al[fb][3], lbase + aoff);
#pragma unroll
            for (int np = 0; np < 2; ++np) {
                uint32_t off = (uint32_t)((bnrow + np * 16) * SROW + k0 + bkof) * 2;
                ldsm4(bh[fb][np][0], bh[fb][np][1], bh[fb][np][2], bh[fb][np][3],
                      sbase + B_H * 2 + off);
                ldsm4(bl[fb][np][0], bl[fb][np][1], bl[fb][np][2], bl[fb][np][3],
                      sbase + B_L * 2 + off);
            }
        };

        ldfr(0, 0);
#pragma unroll
        for (int ks = 0; ks < 8; ++ks) {
            int fb = ks & 1;
            if (ks < 7) ldfr(ks + 1, fb ^ 1);
#pragma unroll
            for (int nt = 0; nt < 4; ++nt) {
                const uint32_t* bhp = &bh[fb][nt >> 1][(nt & 1) * 2];
                const uint32_t* blp = &bl[fb][nt >> 1][(nt & 1) * 2];
                mma_bf16(acc[nt], ah[fb], bhp);
                mma_bf16(acc[nt], ah[fb], blp);
                mma_bf16(acc[nt], al[fb], bhp);
            }
        }

        // epilogue for this panel
        int row = bm * 32 + wm * 16 + grp;
#pragma unroll
        for (int nt = 0; nt < 4; ++nt) {
            int col = bn * 128 + wn * 32 + nt * 8 + qp * 2;
            float2 v0 = {acc[nt][0] + bv[nt].x, acc[nt][1] + bv[nt].y};
            float2 v1 = {acc[nt][2] + bv[nt].x, acc[nt][3] + bv[nt].y};
            *(float2*)(C + (size_t)row * Nc + col) = v0;
            *(float2*)(C + (size_t)(row + 8) * Nc + col) = v1;
        }
        __syncthreads();   // all reads of A[buf] done before it is refilled
        buf ^= 1;
    }
}

// ---------------- fused edge message + deterministic aggregation ----------------
__global__ __launch_bounds__(128) void k_edge(const float* __restrict__ Wmsg,
                                              const float* __restrict__ bmsg) {
    int lane = threadIdx.x & 31;
    int nl = threadIdx.x >> 5;
    int n = blockIdx.x * 4 + nl;
    int b = blockIdx.y;
    float4 we = *(const float4*)(Wmsg + 256 * 128 + lane * 4);
    float4 bm = *(const float4*)(bmsg + lane * 4);
    const float* bigb = g_big + (size_t)b * NN * 640;
    float4 ht = *(const float4*)(bigb + (size_t)n * 640 + 128 + lane * 4);
    float4 base = {ht.x + bm.x, ht.y + bm.y, ht.z + bm.z, ht.w + bm.w};
    const float* efb = g_ef + (size_t)b * EE;
    int s0 = g_off[n], s1 = g_off[n + 1];
    float4 acc = {0.f, 0.f, 0.f, 0.f};
    int s = s0;
    for (; s + 2 <= s1; s += 2) {
        int sr0 = g_esrc[s], sr1 = g_esrc[s + 1];
        float e0 = efb[s], e1 = efb[s + 1];
        float4 h0 = *(const float4*)(bigb + (size_t)sr0 * 640 + lane * 4);
        float4 h1 = *(const float4*)(bigb + (size_t)sr1 * 640 + lane * 4);
        acc.x += selu_f(h0.x + base.x + e0 * we.x) + selu_f(h1.x + base.x + e1 * we.x);
        acc.y += selu_f(h0.y + base.y + e0 * we.y) + selu_f(h1.y + base.y + e1 * we.y);
        acc.z += selu_f(h0.z + base.z + e0 * we.z) + selu_f(h1.z + base.z + e1 * we.z);
        acc.w += selu_f(h0.w + base.w + e0 * we.w) + selu_f(h1.w + base.w + e1 * we.w);
    }
    if (s < s1) {
        int sr0 = g_esrc[s];
        float e0 = efb[s];
        float4 h0 = *(const float4*)(bigb + (size_t)sr0 * 640 + lane * 4);
        acc.x += selu_f(h0.x + base.x + e0 * we.x);
        acc.y += selu_f(h0.y + base.y + e0 * we.y);
        acc.z += selu_f(h0.z + base.z + e0 * we.z);
        acc.w += selu_f(h0.w + base.w + e0 * we.w);
    }
    // write bf16 hi/lo (consumed by k_mm<384>)
    size_t o = ((size_t)(b * NN + n)) * DD + lane * 4;
    float a4[4] = {acc.x, acc.y, acc.z, acc.w};
    __nv_bfloat16 hi4[4], lo4[4];
#pragma unroll
    for (int j = 0; j < 4; ++j) {
        hi4[j] = __float2bfloat16(a4[j]);
        lo4[j] = __float2bfloat16(a4[j] - __bfloat162float(hi4[j]));
    }
    *(uint2*)(g_aggh + o) = *(uint2*)hi4;
    *(uint2*)(g_aggl + o) = *(uint2*)lo4;
}

// ---------------- GRU elementwise ----------------
__global__ void k_gru(const float* __restrict__ hprev) {
    int t = blockIdx.x * blockDim.x + threadIdx.x;
    if (t >= BB * NN * DD) return;
    int row = t >> 7, d = t & 127;
    const float* gi = g_gi + (size_t)row * 384;
    const float* gh = g_big + (size_t)row * 640 + 256;
    float ir = gi[d], iz = gi[128 + d], in_ = gi[256 + d];
    float hr = gh[d], hz = gh[128 + d], hn = gh[256 + d];
    float h = hprev[t];
    float r = 1.f / (1.f + __expf(-(ir + hr)));
    float z = 1.f / (1.f + __expf(-(iz + hz)));
    float nv = tanhf(in_ + r * hn);
    float hn2 = (1.f - z) * nv + z * h;
    g_h[t] = hn2;
    __nv_bfloat16 hi = __float2bfloat16(hn2);
    g_hh[t] = hi;
    g_hl[t] = __float2bfloat16(hn2 - __bfloat162float(hi));
}

// ---------------- pooling + readout head ----------------
__global__ void k_pool() {
    int c = blockIdx.x, b = blockIdx.y, d = threadIdx.x;
    const float* hb = g_h + ((size_t)b * NN + c * 64) * DD + d;
    float s = 0.f;
#pragma unroll 8
    for (int n = 0; n < 64; ++n) s += hb[(size_t)n * DD];
    g_part[(b * 16 + c) * DD + d] = s;
}

__global__ void k_head(const float* __restrict__ Wr1, const float* __restrict__ br1,
                       const float* __restrict__ Wr2, const float* __restrict__ br2,
                       const float* __restrict__ Wpol, const float* __restrict__ bpol,
                       float* __restrict__ out) {
    int b = blockIdx.x, d = threadIdx.x;
    __shared__ float p[128], q[128];
    float s = 0.f;
#pragma unroll
    for (int c = 0; c < 16; ++c) s += g_part[(b * 16 + c) * DD + d];
    p[d] = s;
    __syncthreads();
    float y = br1[d];
#pragma unroll 8
    for (int k = 0; k < 128; ++k) y = fmaf(p[k], Wr1[k * 128 + d], y);
    q[d] = selu_f(y);
    __syncthreads();
    y = br2[d];
#pragma unroll 8
    for (int k = 0; k < 128; ++k) y = fmaf(q[k], Wr2[k * 128 + d], y);
    float p2 = selu_f(y);
    __syncthreads();
    p[d] = p2;
    __syncthreads();
    if (d < 64) {
        float o = bpol[d];
#pragma unroll 8
        for (int k = 0; k < 128; ++k) o = fmaf(p[k], Wpol[k * 64 + d], o);
        out[b * 64 + d] = o;
    }
}

// ---------------- launch ----------------
extern "C" void kernel_launch(void* const* d_in, const int* in_sizes, int n_in,
                              void* d_out, int out_size) {
    const float* nf   = (const float*)d_in[0];
    const float* edge = (const float*)d_in[1];
    const int*   src  = (const int*)d_in[2];
    const int*   tgt  = (const int*)d_in[3];
    const float* Wmsg = (const float*)d_in[4];
    const float* bmsg = (const float*)d_in[5];
    const float* Wih  = (const float*)d_in[6];
    const float* Whh  = (const float*)d_in[7];
    const float* bih  = (const float*)d_in[8];
    const float* bhh  = (const float*)d_in[9];
    const float* Wr1  = (const float*)d_in[10];
    const float* br1  = (const float*)d_in[11];
    const float* Wr2  = (const float*)d_in[12];
    const float* br2  = (const float*)d_in[13];
    const float* Wpol = (const float*)d_in[14];
    const float* bpol = (const float*)d_in[15];
    float* out = (float*)d_out;

    float *g_h_p, *g_big_p, *g_gi_p, *g_bias1_p;
    __nv_bfloat16 *wbh_p, *wbl_p, *wih_h_p, *wih_l_p, *hh_p, *hl_p, *aggh_p, *aggl_p;
    cudaGetSymbolAddress((void**)&g_h_p, g_h);
    cudaGetSymbolAddress((void**)&g_big_p, g_big);
    cudaGetSymbolAddress((void**)&g_gi_p, g_gi);
    cudaGetSymbolAddress((void**)&g_bias1_p, g_bias1);
    cudaGetSymbolAddress((void**)&wbh_p, g_Wbh);
    cudaGetSymbolAddress((void**)&wbl_p, g_Wbl);
    cudaGetSymbolAddress((void**)&wih_h_p, g_Wih_h);
    cudaGetSymbolAddress((void**)&wih_l_p, g_Wih_l);
    cudaGetSymbolAddress((void**)&hh_p, g_hh);
    cudaGetSymbolAddress((void**)&hl_p, g_hl);
    cudaGetSymbolAddress((void**)&aggh_p, g_aggh);
    cudaGetSymbolAddress((void**)&aggl_p, g_aggl);

    cudaFuncSetAttribute(k_mm<640>, cudaFuncAttributeMaxDynamicSharedMemorySize, MM_SMEM);
    cudaFuncSetAttribute(k_mm<384>, cudaFuncAttributeMaxDynamicSharedMemorySize, MM_SMEM);

    // launch index 3 == first k_mm<640> (profiled)
    k_pack<<<320, 256>>>(Wmsg, Whh, bhh, Wih);
    k_cnt<<<CH, 256>>>(tgt);
    k_hcvt<<<(BB * NN * DD + 255) / 256, 256>>>(nf);
    k_mm<640><<<dim3(5, 59), 256, MM_SMEM>>>(hh_p, hl_p, wbh_p, wbl_p, g_bias1_p, g_big_p);
    k_tot<<<8, 128>>>();
    k_scanx<<<1, NN>>>();
    k_offk<<<8, 128>>>();
    k_fill<<<CH, 32>>>(tgt, src);
    k_ef<<<(BB * EE + 255) / 256, 256>>>(edge, src, tgt);

    for (int it = 0; it < DIAM; ++it) {
        if (it > 0)
            k_mm<640><<<dim3(5, 59), 256, MM_SMEM>>>(hh_p, hl_p, wbh_p, wbl_p,
                                                     g_bias1_p, g_big_p);
        k_edge<<<dim3(NN / 4, BB), 128>>>(Wmsg, bmsg);
        k_mm<384><<<dim3(3, 98), 256, MM_SMEM>>>(aggh_p, aggl_p, wih_h_p, wih_l_p,
                                                 bih, g_gi_p);
        k_gru<<<(BB * NN * DD + 255) / 256, 256>>>(it == 0 ? nf : g_h_p);
    }

    k_pool<<<dim3(16, BB), 128>>>();
    k_head<<<BB, 128>>>(Wr1, br1, Wr2, br2, Wpol, bpol, out);
}